// round 1
// baseline (speedup 1.0000x reference)
#include <cuda_runtime.h>
#include <math.h>

#define BATCH 4
#define SEQ   2048
#define DIM   1024

// ---------------- scratch (static device globals; no allocation) ----------------
__device__ float g_Q[BATCH * SEQ * DIM];
__device__ float g_K[BATCH * SEQ * DIM];
__device__ float g_V[BATCH * SEQ * DIM];
__device__ float g_P[(long long)BATCH * SEQ * SEQ];  // scores, then probs (in-place)
__device__ int   g_mask_is_i32;

// ---------------- mask dtype detector ----------------
// If the bool mask is stored as int32, every 4-byte word is 0 or 1.
// If stored as uint8 (packed bools), P(1024 words all in {0,1}) ~ 8^-1024.
__global__ void detect_mask_kernel(const int* __restrict__ mask_words) {
    if (blockIdx.x == 0 && threadIdx.x == 0) {
        int ok = 1;
        for (int i = 0; i < 1024; i++) {
            int v = mask_words[i];
            if (v != 0 && v != 1) { ok = 0; break; }
        }
        g_mask_is_i32 = ok;
    }
}

// ---------------- SGEMM NN: C[M,N] = A[M,K] @ B[K,N], row-major ----------------
// 128x128 block tile, BK=8, 256 threads, 8x8 per-thread microtile.
__global__ __launch_bounds__(256)
void sgemm_nn(const float* __restrict__ A, const float* __restrict__ Bm,
              float* __restrict__ C, int M, int N, int K,
              long long strideA, long long strideB, long long strideC)
{
    A  += (long long)blockIdx.z * strideA;
    Bm += (long long)blockIdx.z * strideB;
    C  += (long long)blockIdx.z * strideC;

    __shared__ float As[8][128];
    __shared__ float Bs[8][128];

    const int t    = threadIdx.x;
    const int row0 = blockIdx.y * 128;
    const int col0 = blockIdx.x * 128;

    const int aRow = t >> 1;         // 0..127
    const int aCol = (t & 1) * 4;    // 0 or 4
    const int bRow = t >> 5;         // 0..7
    const int bCol = (t & 31) * 4;   // 0..124
    const int ty   = t >> 4;         // 0..15
    const int tx   = t & 15;         // 0..15

    float acc[8][8];
#pragma unroll
    for (int i = 0; i < 8; i++)
#pragma unroll
        for (int j = 0; j < 8; j++) acc[i][j] = 0.f;

    for (int kk = 0; kk < K; kk += 8) {
        float4 a4 = *(const float4*)(A + (long long)(row0 + aRow) * K + kk + aCol);
        As[aCol + 0][aRow] = a4.x;
        As[aCol + 1][aRow] = a4.y;
        As[aCol + 2][aRow] = a4.z;
        As[aCol + 3][aRow] = a4.w;
        float4 b4 = *(const float4*)(Bm + (long long)(kk + bRow) * N + col0 + bCol);
        *(float4*)&Bs[bRow][bCol] = b4;
        __syncthreads();

#pragma unroll
        for (int k = 0; k < 8; k++) {
            float4 a0 = *(const float4*)&As[k][ty * 8];
            float4 a1 = *(const float4*)&As[k][ty * 8 + 4];
            float4 b0 = *(const float4*)&Bs[k][tx * 8];
            float4 b1 = *(const float4*)&Bs[k][tx * 8 + 4];
            float av[8] = {a0.x, a0.y, a0.z, a0.w, a1.x, a1.y, a1.z, a1.w};
            float bv[8] = {b0.x, b0.y, b0.z, b0.w, b1.x, b1.y, b1.z, b1.w};
#pragma unroll
            for (int i = 0; i < 8; i++)
#pragma unroll
                for (int j = 0; j < 8; j++)
                    acc[i][j] = fmaf(av[i], bv[j], acc[i][j]);
        }
        __syncthreads();
    }

#pragma unroll
    for (int i = 0; i < 8; i++) {
        float4* cp = (float4*)(C + (long long)(row0 + ty * 8 + i) * N + col0 + tx * 8);
        cp[0] = make_float4(acc[i][0], acc[i][1], acc[i][2], acc[i][3]);
        cp[1] = make_float4(acc[i][4], acc[i][5], acc[i][6], acc[i][7]);
    }
}

// ---------------- SGEMM NT: C[M,N] = A[M,K] @ B2[N,K]^T, row-major ----------------
__global__ __launch_bounds__(256)
void sgemm_nt(const float* __restrict__ A, const float* __restrict__ B2,
              float* __restrict__ C, int M, int N, int K,
              long long strideA, long long strideB, long long strideC)
{
    A  += (long long)blockIdx.z * strideA;
    B2 += (long long)blockIdx.z * strideB;
    C  += (long long)blockIdx.z * strideC;

    __shared__ float As[8][128];
    __shared__ float Bs[8][128];

    const int t    = threadIdx.x;
    const int row0 = blockIdx.y * 128;
    const int col0 = blockIdx.x * 128;

    const int aRow = t >> 1;
    const int aCol = (t & 1) * 4;
    const int ty   = t >> 4;
    const int tx   = t & 15;

    float acc[8][8];
#pragma unroll
    for (int i = 0; i < 8; i++)
#pragma unroll
        for (int j = 0; j < 8; j++) acc[i][j] = 0.f;

    for (int kk = 0; kk < K; kk += 8) {
        float4 a4 = *(const float4*)(A + (long long)(row0 + aRow) * K + kk + aCol);
        As[aCol + 0][aRow] = a4.x;
        As[aCol + 1][aRow] = a4.y;
        As[aCol + 2][aRow] = a4.z;
        As[aCol + 3][aRow] = a4.w;
        // B tile: Bs[k][j] = B2[col0+j][kk+k]
        float4 b4 = *(const float4*)(B2 + (long long)(col0 + aRow) * K + kk + aCol);
        Bs[aCol + 0][aRow] = b4.x;
        Bs[aCol + 1][aRow] = b4.y;
        Bs[aCol + 2][aRow] = b4.z;
        Bs[aCol + 3][aRow] = b4.w;
        __syncthreads();

#pragma unroll
        for (int k = 0; k < 8; k++) {
            float4 a0 = *(const float4*)&As[k][ty * 8];
            float4 a1 = *(const float4*)&As[k][ty * 8 + 4];
            float4 b0 = *(const float4*)&Bs[k][tx * 8];
            float4 b1 = *(const float4*)&Bs[k][tx * 8 + 4];
            float av[8] = {a0.x, a0.y, a0.z, a0.w, a1.x, a1.y, a1.z, a1.w};
            float bv[8] = {b0.x, b0.y, b0.z, b0.w, b1.x, b1.y, b1.z, b1.w};
#pragma unroll
            for (int i = 0; i < 8; i++)
#pragma unroll
                for (int j = 0; j < 8; j++)
                    acc[i][j] = fmaf(av[i], bv[j], acc[i][j]);
        }
        __syncthreads();
    }

#pragma unroll
    for (int i = 0; i < 8; i++) {
        float4* cp = (float4*)(C + (long long)(row0 + ty * 8 + i) * N + col0 + tx * 8);
        cp[0] = make_float4(acc[i][0], acc[i][1], acc[i][2], acc[i][3]);
        cp[1] = make_float4(acc[i][4], acc[i][5], acc[i][6], acc[i][7]);
    }
}

// ---------------- masked, scaled softmax over rows of g_P (in-place) ----------------
__global__ __launch_bounds__(256)
void softmax_kernel(const void* __restrict__ maskp, float* __restrict__ P)
{
    const int t = threadIdx.x;
    const int q = blockIdx.x;
    const int b = blockIdx.y;

    float* row = P + ((long long)b * SEQ + q) * (long long)SEQ;
    const bool i32 = (g_mask_is_i32 != 0);
    const unsigned char* m8  = (const unsigned char*)maskp + (long long)q * SEQ;
    const int*           m32 = (const int*)maskp           + (long long)q * SEQ;

    float v[8];
    float mx = -INFINITY;
#pragma unroll
    for (int i = 0; i < 8; i++) {
        int j = t + i * 256;
        bool mk = i32 ? (m32[j] != 0) : (m8[j] != 0);
        float s = mk ? -INFINITY : row[j] * 0.03125f;  // 1/sqrt(1024)
        v[i] = s;
        mx = fmaxf(mx, s);
    }

    __shared__ float red[256];
    red[t] = mx;
    __syncthreads();
    for (int s = 128; s > 0; s >>= 1) {
        if (t < s) red[t] = fmaxf(red[t], red[t + s]);
        __syncthreads();
    }
    mx = red[0];
    __syncthreads();

    float sum = 0.f;
#pragma unroll
    for (int i = 0; i < 8; i++) {
        float e = expf(v[i] - mx);   // expf(-inf - mx) = 0
        v[i] = e;
        sum += e;
    }
    red[t] = sum;
    __syncthreads();
    for (int s = 128; s > 0; s >>= 1) {
        if (t < s) red[t] += red[t + s];
        __syncthreads();
    }
    float inv = 1.0f / red[0];

#pragma unroll
    for (int i = 0; i < 8; i++)
        row[t + i * 256] = v[i] * inv;
}

// ---------------- launch ----------------
extern "C" void kernel_launch(void* const* d_in, const int* in_sizes, int n_in,
                              void* d_out, int out_size)
{
    const float* x    = (const float*)d_in[0];
    const void*  mask = d_in[1];
    const float* wq   = (const float*)d_in[2];
    const float* wk   = (const float*)d_in[3];
    const float* wv   = (const float*)d_in[4];
    float*       out  = (float*)d_out;

    float *Q, *K, *V, *P;
    cudaGetSymbolAddress((void**)&Q, g_Q);
    cudaGetSymbolAddress((void**)&K, g_K);
    cudaGetSymbolAddress((void**)&V, g_V);
    cudaGetSymbolAddress((void**)&P, g_P);

    // 1) mask dtype detection
    detect_mask_kernel<<<1, 32>>>((const int*)mask);

    // 2) projections: [B*S, D] @ [D, D]  (M=8192, N=1024, K=1024)
    {
        dim3 grid(DIM / 128, (BATCH * SEQ) / 128, 1);
        sgemm_nn<<<grid, 256>>>(x, wq, Q, BATCH * SEQ, DIM, DIM, 0, 0, 0);
        sgemm_nn<<<grid, 256>>>(x, wk, K, BATCH * SEQ, DIM, DIM, 0, 0, 0);
        sgemm_nn<<<grid, 256>>>(x, wv, V, BATCH * SEQ, DIM, DIM, 0, 0, 0);
    }

    // 3) scores: per batch, S = Q @ K^T  (M=N=2048, K=1024)
    {
        dim3 grid(SEQ / 128, SEQ / 128, BATCH);
        sgemm_nt<<<grid, 256>>>(Q, K, P, SEQ, SEQ, DIM,
                                (long long)SEQ * DIM, (long long)SEQ * DIM,
                                (long long)SEQ * SEQ);
    }

    // 4) masked scaled softmax (in-place on P)
    {
        dim3 grid(SEQ, BATCH);
        softmax_kernel<<<grid, 256>>>(mask, P);
    }

    // 5) output: per batch, O = P @ V  (M=2048, N=1024, K=2048)
    {
        dim3 grid(DIM / 128, SEQ / 128, BATCH);
        sgemm_nn<<<grid, 256>>>(P, V, out, SEQ, DIM, SEQ,
                                (long long)SEQ * SEQ, (long long)SEQ * DIM,
                                (long long)SEQ * DIM);
    }
}

// round 2
// speedup vs baseline: 1.0028x; 1.0028x over previous
#include <cuda_runtime.h>
#include <math.h>

#define BATCH 4
#define SEQ   2048
#define DIM   1024

// ---------------- scratch (static device globals; no allocation) ----------------
__device__ float g_Q[BATCH * SEQ * DIM];
__device__ float g_K[BATCH * SEQ * DIM];
__device__ float g_V[BATCH * SEQ * DIM];
__device__ float g_P[(long long)BATCH * SEQ * SEQ];  // scores, then probs (in-place)
__device__ int   g_mask_is_i32;

// ---------------- mask dtype detector ----------------
// If the bool mask is stored as int32, every 4-byte word is 0 or 1.
// If stored as uint8 (packed bools), P(1024 words all in {0,1}) ~ 8^-1024.
__global__ void detect_mask_kernel(const int* __restrict__ mask_words) {
    if (blockIdx.x == 0 && threadIdx.x == 0) {
        int ok = 1;
        for (int i = 0; i < 1024; i++) {
            int v = mask_words[i];
            if (v != 0 && v != 1) { ok = 0; break; }
        }
        g_mask_is_i32 = ok;
    }
}

// ---------------- SGEMM NN: C[M,N] = A[M,K] @ B[K,N], row-major ----------------
// 128x128 block tile, BK=8, 256 threads, 8x8 per-thread microtile.
__global__ __launch_bounds__(256)
void sgemm_nn(const float* __restrict__ A, const float* __restrict__ Bm,
              float* __restrict__ C, int M, int N, int K,
              long long strideA, long long strideB, long long strideC)
{
    A  += (long long)blockIdx.z * strideA;
    Bm += (long long)blockIdx.z * strideB;
    C  += (long long)blockIdx.z * strideC;

    __shared__ float As[8][128];
    __shared__ float Bs[8][128];

    const int t    = threadIdx.x;
    const int row0 = blockIdx.y * 128;
    const int col0 = blockIdx.x * 128;

    const int aRow = t >> 1;         // 0..127
    const int aCol = (t & 1) * 4;    // 0 or 4
    const int bRow = t >> 5;         // 0..7
    const int bCol = (t & 31) * 4;   // 0..124
    const int ty   = t >> 4;         // 0..15
    const int tx   = t & 15;         // 0..15

    float acc[8][8];
#pragma unroll
    for (int i = 0; i < 8; i++)
#pragma unroll
        for (int j = 0; j < 8; j++) acc[i][j] = 0.f;

    for (int kk = 0; kk < K; kk += 8) {
        float4 a4 = *(const float4*)(A + (long long)(row0 + aRow) * K + kk + aCol);
        As[aCol + 0][aRow] = a4.x;
        As[aCol + 1][aRow] = a4.y;
        As[aCol + 2][aRow] = a4.z;
        As[aCol + 3][aRow] = a4.w;
        float4 b4 = *(const float4*)(Bm + (long long)(kk + bRow) * N + col0 + bCol);
        *(float4*)&Bs[bRow][bCol] = b4;
        __syncthreads();

#pragma unroll
        for (int k = 0; k < 8; k++) {
            float4 a0 = *(const float4*)&As[k][ty * 8];
            float4 a1 = *(const float4*)&As[k][ty * 8 + 4];
            float4 b0 = *(const float4*)&Bs[k][tx * 8];
            float4 b1 = *(const float4*)&Bs[k][tx * 8 + 4];
            float av[8] = {a0.x, a0.y, a0.z, a0.w, a1.x, a1.y, a1.z, a1.w};
            float bv[8] = {b0.x, b0.y, b0.z, b0.w, b1.x, b1.y, b1.z, b1.w};
#pragma unroll
            for (int i = 0; i < 8; i++)
#pragma unroll
                for (int j = 0; j < 8; j++)
                    acc[i][j] = fmaf(av[i], bv[j], acc[i][j]);
        }
        __syncthreads();
    }

#pragma unroll
    for (int i = 0; i < 8; i++) {
        float4* cp = (float4*)(C + (long long)(row0 + ty * 8 + i) * N + col0 + tx * 8);
        cp[0] = make_float4(acc[i][0], acc[i][1], acc[i][2], acc[i][3]);
        cp[1] = make_float4(acc[i][4], acc[i][5], acc[i][6], acc[i][7]);
    }
}

// ---------------- SGEMM NT: C[M,N] = A[M,K] @ B2[N,K]^T, row-major ----------------
__global__ __launch_bounds__(256)
void sgemm_nt(const float* __restrict__ A, const float* __restrict__ B2,
              float* __restrict__ C, int M, int N, int K,
              long long strideA, long long strideB, long long strideC)
{
    A  += (long long)blockIdx.z * strideA;
    B2 += (long long)blockIdx.z * strideB;
    C  += (long long)blockIdx.z * strideC;

    __shared__ float As[8][128];
    __shared__ float Bs[8][128];

    const int t    = threadIdx.x;
    const int row0 = blockIdx.y * 128;
    const int col0 = blockIdx.x * 128;

    const int aRow = t >> 1;
    const int aCol = (t & 1) * 4;
    const int ty   = t >> 4;
    const int tx   = t & 15;

    float acc[8][8];
#pragma unroll
    for (int i = 0; i < 8; i++)
#pragma unroll
        for (int j = 0; j < 8; j++) acc[i][j] = 0.f;

    for (int kk = 0; kk < K; kk += 8) {
        float4 a4 = *(const float4*)(A + (long long)(row0 + aRow) * K + kk + aCol);
        As[aCol + 0][aRow] = a4.x;
        As[aCol + 1][aRow] = a4.y;
        As[aCol + 2][aRow] = a4.z;
        As[aCol + 3][aRow] = a4.w;
        // B tile: Bs[k][j] = B2[col0+j][kk+k]
        float4 b4 = *(const float4*)(B2 + (long long)(col0 + aRow) * K + kk + aCol);
        Bs[aCol + 0][aRow] = b4.x;
        Bs[aCol + 1][aRow] = b4.y;
        Bs[aCol + 2][aRow] = b4.z;
        Bs[aCol + 3][aRow] = b4.w;
        __syncthreads();

#pragma unroll
        for (int k = 0; k < 8; k++) {
            float4 a0 = *(const float4*)&As[k][ty * 8];
            float4 a1 = *(const float4*)&As[k][ty * 8 + 4];
            float4 b0 = *(const float4*)&Bs[k][tx * 8];
            float4 b1 = *(const float4*)&Bs[k][tx * 8 + 4];
            float av[8] = {a0.x, a0.y, a0.z, a0.w, a1.x, a1.y, a1.z, a1.w};
            float bv[8] = {b0.x, b0.y, b0.z, b0.w, b1.x, b1.y, b1.z, b1.w};
#pragma unroll
            for (int i = 0; i < 8; i++)
#pragma unroll
                for (int j = 0; j < 8; j++)
                    acc[i][j] = fmaf(av[i], bv[j], acc[i][j]);
        }
        __syncthreads();
    }

#pragma unroll
    for (int i = 0; i < 8; i++) {
        float4* cp = (float4*)(C + (long long)(row0 + ty * 8 + i) * N + col0 + tx * 8);
        cp[0] = make_float4(acc[i][0], acc[i][1], acc[i][2], acc[i][3]);
        cp[1] = make_float4(acc[i][4], acc[i][5], acc[i][6], acc[i][7]);
    }
}

// ---------------- masked, scaled softmax over rows of g_P (in-place) ----------------
__global__ __launch_bounds__(256)
void softmax_kernel(const void* __restrict__ maskp, float* __restrict__ P)
{
    const int t = threadIdx.x;
    const int q = blockIdx.x;
    const int b = blockIdx.y;

    float* row = P + ((long long)b * SEQ + q) * (long long)SEQ;
    const bool i32 = (g_mask_is_i32 != 0);
    const unsigned char* m8  = (const unsigned char*)maskp + (long long)q * SEQ;
    const int*           m32 = (const int*)maskp           + (long long)q * SEQ;

    float v[8];
    float mx = -INFINITY;
#pragma unroll
    for (int i = 0; i < 8; i++) {
        int j = t + i * 256;
        bool mk = i32 ? (m32[j] != 0) : (m8[j] != 0);
        float s = mk ? -INFINITY : row[j] * 0.03125f;  // 1/sqrt(1024)
        v[i] = s;
        mx = fmaxf(mx, s);
    }

    __shared__ float red[256];
    red[t] = mx;
    __syncthreads();
    for (int s = 128; s > 0; s >>= 1) {
        if (t < s) red[t] = fmaxf(red[t], red[t + s]);
        __syncthreads();
    }
    mx = red[0];
    __syncthreads();

    float sum = 0.f;
#pragma unroll
    for (int i = 0; i < 8; i++) {
        float e = expf(v[i] - mx);   // expf(-inf - mx) = 0
        v[i] = e;
        sum += e;
    }
    red[t] = sum;
    __syncthreads();
    for (int s = 128; s > 0; s >>= 1) {
        if (t < s) red[t] += red[t + s];
        __syncthreads();
    }
    float inv = 1.0f / red[0];

#pragma unroll
    for (int i = 0; i < 8; i++)
        row[t + i * 256] = v[i] * inv;
}

// ---------------- launch ----------------
extern "C" void kernel_launch(void* const* d_in, const int* in_sizes, int n_in,
                              void* d_out, int out_size)
{
    const float* x    = (const float*)d_in[0];
    const void*  mask = d_in[1];
    const float* wq   = (const float*)d_in[2];
    const float* wk   = (const float*)d_in[3];
    const float* wv   = (const float*)d_in[4];
    float*       out  = (float*)d_out;

    float *Q, *K, *V, *P;
    cudaGetSymbolAddress((void**)&Q, g_Q);
    cudaGetSymbolAddress((void**)&K, g_K);
    cudaGetSymbolAddress((void**)&V, g_V);
    cudaGetSymbolAddress((void**)&P, g_P);

    // 1) mask dtype detection
    detect_mask_kernel<<<1, 32>>>((const int*)mask);

    // 2) projections: [B*S, D] @ [D, D]  (M=8192, N=1024, K=1024)
    {
        dim3 grid(DIM / 128, (BATCH * SEQ) / 128, 1);
        sgemm_nn<<<grid, 256>>>(x, wq, Q, BATCH * SEQ, DIM, DIM, 0, 0, 0);
        sgemm_nn<<<grid, 256>>>(x, wk, K, BATCH * SEQ, DIM, DIM, 0, 0, 0);
        sgemm_nn<<<grid, 256>>>(x, wv, V, BATCH * SEQ, DIM, DIM, 0, 0, 0);
    }

    // 3) scores: per batch, S = Q @ K^T  (M=N=2048, K=1024)
    {
        dim3 grid(SEQ / 128, SEQ / 128, BATCH);
        sgemm_nt<<<grid, 256>>>(Q, K, P, SEQ, SEQ, DIM,
                                (long long)SEQ * DIM, (long long)SEQ * DIM,
                                (long long)SEQ * SEQ);
    }

    // 4) masked scaled softmax (in-place on P)
    {
        dim3 grid(SEQ, BATCH);
        softmax_kernel<<<grid, 256>>>(mask, P);
    }

    // 5) output: per batch, O = P @ V  (M=2048, N=1024, K=2048)
    {
        dim3 grid(DIM / 128, SEQ / 128, BATCH);
        sgemm_nn<<<grid, 256>>>(P, V, out, SEQ, DIM, SEQ,
                                (long long)SEQ * SEQ, (long long)SEQ * DIM,
                                (long long)SEQ * DIM);
    }
}

// round 4
// speedup vs baseline: 1.5671x; 1.5627x over previous
#include <cuda_runtime.h>
#include <math.h>
#include <stdint.h>

#define BATCH 4
#define SEQ   2048
#define DIM   1024

// ---------------- GEMM tile configuration ----------------
#define BM 128
#define BN 128
#define BK 32
#define SROW 36                        // padded smem row stride in floats (144B, 16B-aligned)
#define TILE_F (128 * SROW)            // 4608 floats per tile
#define STAGE_F (4 * TILE_F)           // Ah, Al, Bh, Bl
#define GEMM_SMEM (2 * STAGE_F * 4)    // bytes: 2 stages = 147456

// ---------------- scratch (static device globals) ----------------
__device__ float g_x_hi[BATCH * SEQ * DIM];
__device__ float g_x_lo[BATCH * SEQ * DIM];
__device__ float g_Wq_hi[DIM * DIM];   // transposed: [n][k]
__device__ float g_Wq_lo[DIM * DIM];
__device__ float g_Wk_hi[DIM * DIM];
__device__ float g_Wk_lo[DIM * DIM];
__device__ float g_Wv_hi[DIM * DIM];
__device__ float g_Wv_lo[DIM * DIM];
__device__ float g_Q_hi[BATCH * SEQ * DIM];
__device__ float g_Q_lo[BATCH * SEQ * DIM];
__device__ float g_K_hi[BATCH * SEQ * DIM];
__device__ float g_K_lo[BATCH * SEQ * DIM];
__device__ float g_Vt_hi[BATCH * DIM * SEQ];   // [b][dim][seq]
__device__ float g_Vt_lo[BATCH * DIM * SEQ];
__device__ float g_P  [(long long)BATCH * SEQ * SEQ];
__device__ float g_P_hi[(long long)BATCH * SEQ * SEQ];
__device__ int   g_mask_is_i32;

// ---------------- helpers ----------------
__device__ __forceinline__ uint32_t smem_u32(const void* p) {
    uint32_t a;
    asm("{ .reg .u64 t; cvta.to.shared.u64 t, %1; cvt.u32.u64 %0, t; }" : "=r"(a) : "l"(p));
    return a;
}
__device__ __forceinline__ float f32_to_tf32(float x) {
    uint32_t u;
    asm("cvt.rna.tf32.f32 %0, %1;" : "=r"(u) : "f"(x));
    return __uint_as_float(u);
}
__device__ __forceinline__ void cpasync16(uint32_t dst, const float* src) {
    asm volatile("{ .reg .u64 g; cvta.to.global.u64 g, %1; "
                 "cp.async.cg.shared.global [%0], [g], 16; }"
                 :: "r"(dst), "l"(src) : "memory");
}
__device__ __forceinline__ void cp_commit() {
    asm volatile("cp.async.commit_group;" ::: "memory");
}
// mma.m16n8k8 tf32: D += A(16x8,row) * B(8x8,col)
__device__ __forceinline__ void mma8(float* c, const uint32_t* a, const uint32_t* b) {
    asm volatile(
        "mma.sync.aligned.m16n8k8.row.col.f32.tf32.tf32.f32 "
        "{%0,%1,%2,%3}, {%4,%5,%6,%7}, {%8,%9}, {%0,%1,%2,%3};"
        : "+f"(c[0]), "+f"(c[1]), "+f"(c[2]), "+f"(c[3])
        : "r"(a[0]), "r"(a[1]), "r"(a[2]), "r"(a[3]), "r"(b[0]), "r"(b[1]));
}

// ============================================================================
// tf32 split NT GEMM: C[m,n] = sum_k A[m,k]*B[n,k]
//   PM bit0: Ah*Bh   bit1: Ah*Bl   bit2: Al*Bh
//   split_out: 0 -> fp32 C; 1 -> C=rna(v), C2=rna(v-C)
// ============================================================================
template <int PM>
__global__ __launch_bounds__(256, 1)
void mma_gemm(const float* __restrict__ Ah, const float* __restrict__ Al,
              const float* __restrict__ Bh, const float* __restrict__ Bl,
              float* __restrict__ C, float* __restrict__ C2,
              int Kdim, int ldC,
              long long sA, long long sB, long long sC, int split_out)
{
    extern __shared__ float sm[];
    const int tid  = threadIdx.x;
    const int wid  = tid >> 5;
    const int lane = tid & 31;
    const int gid  = lane >> 2;    // 0..7
    const int tg   = lane & 3;     // 0..3
    const int wm   = wid & 1;      // 2 warps in m
    const int wn   = wid >> 1;     // 4 warps in n

    Ah += blockIdx.z * sA;
    if (PM & 4) Al += blockIdx.z * sA;
    Bh += blockIdx.z * sB;
    if (PM & 2) Bl += blockIdx.z * sB;
    C += blockIdx.z * sC;
    if (C2) C2 += blockIdx.z * sC;

    const int row0 = blockIdx.y * BM;
    const int col0 = blockIdx.x * BN;
    const int NC   = Kdim / BK;
    const uint32_t sbase = smem_u32(sm);

    float acc[4][4][4];
#pragma unroll
    for (int i = 0; i < 4; i++)
#pragma unroll
        for (int j = 0; j < 4; j++)
#pragma unroll
            for (int r = 0; r < 4; r++) acc[i][j][r] = 0.f;

    // ---- async tile loader ----
    auto issue = [&](int c, int buf) {
        const int kk = c * BK;
        const uint32_t st = sbase + (uint32_t)buf * (STAGE_F * 4);
#pragma unroll
        for (int i = 0; i < 4; i++) {
            const int idx = tid + i * 256;
            const int r   = idx >> 3;
            const int c4  = idx & 7;
            const uint32_t so = (uint32_t)(r * (SROW * 4) + c4 * 16);
            const long long goA = (long long)(row0 + r) * Kdim + kk + c4 * 4;
            const long long goB = (long long)(col0 + r) * Kdim + kk + c4 * 4;
            cpasync16(st + so, Ah + goA);
            if (PM & 4) cpasync16(st + TILE_F * 4 + so, Al + goA);
            cpasync16(st + 2 * TILE_F * 4 + so, Bh + goB);
            if (PM & 2) cpasync16(st + 3 * TILE_F * 4 + so, Bl + goB);
        }
        cp_commit();
    };

    issue(0, 0);
    issue(1, 1);

    for (int c = 0; c < NC; c++) {
        if (c + 1 < NC) asm volatile("cp.async.wait_group 1;" ::: "memory");
        else            asm volatile("cp.async.wait_group 0;" ::: "memory");
        __syncthreads();

        const float* S   = sm + (c & 1) * STAGE_F;
        const float* sAh = S;
        const float* sAl = S + TILE_F;
        const float* sBh = S + 2 * TILE_F;
        const float* sBl = S + 3 * TILE_F;

#pragma unroll
        for (int ks = 0; ks < 4; ks++) {
            const int kc = ks * 8 + tg;
            uint32_t a_h[4][4], a_l[4][4], b_h[4][2], b_l[4][2];
#pragma unroll
            for (int i = 0; i < 4; i++) {
                const int r = wm * 64 + i * 16 + gid;
                a_h[i][0] = __float_as_uint(sAh[r * SROW + kc]);
                a_h[i][1] = __float_as_uint(sAh[(r + 8) * SROW + kc]);
                a_h[i][2] = __float_as_uint(sAh[r * SROW + kc + 4]);
                a_h[i][3] = __float_as_uint(sAh[(r + 8) * SROW + kc + 4]);
                if (PM & 4) {
                    a_l[i][0] = __float_as_uint(sAl[r * SROW + kc]);
                    a_l[i][1] = __float_as_uint(sAl[(r + 8) * SROW + kc]);
                    a_l[i][2] = __float_as_uint(sAl[r * SROW + kc + 4]);
                    a_l[i][3] = __float_as_uint(sAl[(r + 8) * SROW + kc + 4]);
                }
            }
#pragma unroll
            for (int j = 0; j < 4; j++) {
                const int n = wn * 32 + j * 8 + gid;
                b_h[j][0] = __float_as_uint(sBh[n * SROW + kc]);
                b_h[j][1] = __float_as_uint(sBh[n * SROW + kc + 4]);
                if (PM & 2) {
                    b_l[j][0] = __float_as_uint(sBl[n * SROW + kc]);
                    b_l[j][1] = __float_as_uint(sBl[n * SROW + kc + 4]);
                }
            }
#pragma unroll
            for (int i = 0; i < 4; i++)
#pragma unroll
                for (int j = 0; j < 4; j++) {
                    mma8(acc[i][j], a_h[i], b_h[j]);
                    if (PM & 2) mma8(acc[i][j], a_h[i], b_l[j]);
                    if (PM & 4) mma8(acc[i][j], a_l[i], b_h[j]);
                }
        }
        __syncthreads();
        if (c + 2 < NC) issue(c + 2, c & 1);
    }

    // ---- epilogue ----
#pragma unroll
    for (int i = 0; i < 4; i++) {
        const int r0 = row0 + wm * 64 + i * 16 + gid;
#pragma unroll
        for (int j = 0; j < 4; j++) {
            const int cc = col0 + wn * 32 + j * 8 + tg * 2;
            float v0 = acc[i][j][0], v1 = acc[i][j][1];
            float v2 = acc[i][j][2], v3 = acc[i][j][3];
            if (!split_out) {
                *(float2*)(C + (long long)r0 * ldC + cc)       = make_float2(v0, v1);
                *(float2*)(C + (long long)(r0 + 8) * ldC + cc) = make_float2(v2, v3);
            } else {
                float h0 = f32_to_tf32(v0), h1 = f32_to_tf32(v1);
                float h2 = f32_to_tf32(v2), h3 = f32_to_tf32(v3);
                *(float2*)(C  + (long long)r0 * ldC + cc)       = make_float2(h0, h1);
                *(float2*)(C  + (long long)(r0 + 8) * ldC + cc) = make_float2(h2, h3);
                *(float2*)(C2 + (long long)r0 * ldC + cc) =
                    make_float2(f32_to_tf32(v0 - h0), f32_to_tf32(v1 - h1));
                *(float2*)(C2 + (long long)(r0 + 8) * ldC + cc) =
                    make_float2(f32_to_tf32(v2 - h2), f32_to_tf32(v3 - h3));
            }
        }
    }
}

// ---------------- mask dtype detector ----------------
__global__ void detect_mask_kernel(const int* __restrict__ mask_words) {
    if (blockIdx.x == 0 && threadIdx.x == 0) {
        int ok = 1;
        for (int i = 0; i < 1024; i++) {
            int v = mask_words[i];
            if (v != 0 && v != 1) { ok = 0; break; }
        }
        g_mask_is_i32 = ok;
    }
}

// ---------------- elementwise split: x -> (hi, lo), both tf32-rounded ----------------
__global__ __launch_bounds__(256)
void split_kernel(const float4* __restrict__ in, float4* __restrict__ oh,
                  float4* __restrict__ ol, int n4)
{
    int i = blockIdx.x * 256 + threadIdx.x;
    if (i >= n4) return;
    float4 v = in[i];
    float4 h, l;
    h.x = f32_to_tf32(v.x); l.x = f32_to_tf32(v.x - h.x);
    h.y = f32_to_tf32(v.y); l.y = f32_to_tf32(v.y - h.y);
    h.z = f32_to_tf32(v.z); l.z = f32_to_tf32(v.z - h.z);
    h.w = f32_to_tf32(v.w); l.w = f32_to_tf32(v.w - h.w);
    oh[i] = h; ol[i] = l;
}

// ---------------- transpose + split: W[K,N] -> Wt_hi/lo [N,K] ----------------
__global__ __launch_bounds__(256)
void transpose_split_kernel(const float* __restrict__ W,
                            float* __restrict__ Th, float* __restrict__ Tl)
{
    __shared__ float tile[32][33];
    const int n0 = blockIdx.x * 32;
    const int k0 = blockIdx.y * 32;
    const int tx = threadIdx.x, ty = threadIdx.y;
#pragma unroll
    for (int i = 0; i < 4; i++)
        tile[ty + i * 8][tx] = W[(long long)(k0 + ty + i * 8) * DIM + n0 + tx];
    __syncthreads();
#pragma unroll
    for (int i = 0; i < 4; i++) {
        float v = tile[tx][ty + i * 8];
        float h = f32_to_tf32(v);
        long long o = (long long)(n0 + ty + i * 8) * DIM + k0 + tx;
        Th[o] = h;
        Tl[o] = f32_to_tf32(v - h);
    }
}

// ---------------- masked scaled softmax -> tf32-rounded probs ----------------
__global__ __launch_bounds__(256)
void softmax_kernel(const void* __restrict__ maskp,
                    const float* __restrict__ P, float* __restrict__ Ph)
{
    const int t = threadIdx.x;
    const int q = blockIdx.x;
    const int b = blockIdx.y;

    const long long rowoff = ((long long)b * SEQ + q) * (long long)SEQ;
    const float* row = P + rowoff;
    const bool i32 = (g_mask_is_i32 != 0);
    const unsigned char* m8  = (const unsigned char*)maskp + (long long)q * SEQ;
    const int*           m32 = (const int*)maskp           + (long long)q * SEQ;

    float v[8];
    float mx = -INFINITY;
#pragma unroll
    for (int i = 0; i < 8; i++) {
        int j = t + i * 256;
        bool mk = i32 ? (m32[j] != 0) : (m8[j] != 0);
        float s = mk ? -INFINITY : row[j] * 0.03125f;
        v[i] = s;
        mx = fmaxf(mx, s);
    }

    __shared__ float red[256];
    red[t] = mx;
    __syncthreads();
    for (int s = 128; s > 0; s >>= 1) {
        if (t < s) red[t] = fmaxf(red[t], red[t + s]);
        __syncthreads();
    }
    mx = red[0];
    __syncthreads();

    float sum = 0.f;
#pragma unroll
    for (int i = 0; i < 8; i++) {
        float e = expf(v[i] - mx);
        v[i] = e;
        sum += e;
    }
    red[t] = sum;
    __syncthreads();
    for (int s = 128; s > 0; s >>= 1) {
        if (t < s) red[t] += red[t + s];
        __syncthreads();
    }
    float inv = 1.0f / red[0];

#pragma unroll
    for (int i = 0; i < 8; i++)
        Ph[rowoff + t + i * 256] = f32_to_tf32(v[i] * inv);
}

// ---------------- launch ----------------
extern "C" void kernel_launch(void* const* d_in, const int* in_sizes, int n_in,
                              void* d_out, int out_size)
{
    const float* x    = (const float*)d_in[0];
    const void*  mask = d_in[1];
    const float* wq   = (const float*)d_in[2];
    const float* wk   = (const float*)d_in[3];
    const float* wv   = (const float*)d_in[4];
    float*       out  = (float*)d_out;

    float *xh, *xl, *wqh, *wql, *wkh, *wkl, *wvh, *wvl;
    float *Qh, *Ql, *Kh, *Kl, *Vth, *Vtl, *P, *Ph;
    cudaGetSymbolAddress((void**)&xh,  g_x_hi);
    cudaGetSymbolAddress((void**)&xl,  g_x_lo);
    cudaGetSymbolAddress((void**)&wqh, g_Wq_hi);
    cudaGetSymbolAddress((void**)&wql, g_Wq_lo);
    cudaGetSymbolAddress((void**)&wkh, g_Wk_hi);
    cudaGetSymbolAddress((void**)&wkl, g_Wk_lo);
    cudaGetSymbolAddress((void**)&wvh, g_Wv_hi);
    cudaGetSymbolAddress((void**)&wvl, g_Wv_lo);
    cudaGetSymbolAddress((void**)&Qh,  g_Q_hi);
    cudaGetSymbolAddress((void**)&Ql,  g_Q_lo);
    cudaGetSymbolAddress((void**)&Kh,  g_K_hi);
    cudaGetSymbolAddress((void**)&Kl,  g_K_lo);
    cudaGetSymbolAddress((void**)&Vth, g_Vt_hi);
    cudaGetSymbolAddress((void**)&Vtl, g_Vt_lo);
    cudaGetSymbolAddress((void**)&P,   g_P);
    cudaGetSymbolAddress((void**)&Ph,  g_P_hi);

    cudaFuncSetAttribute(mma_gemm<7>,
                         cudaFuncAttributeMaxDynamicSharedMemorySize, GEMM_SMEM);
    cudaFuncSetAttribute(mma_gemm<3>,
                         cudaFuncAttributeMaxDynamicSharedMemorySize, GEMM_SMEM);

    // 1) mask dtype detection
    detect_mask_kernel<<<1, 32>>>((const int*)mask);

    // 2) split x; transpose+split weights
    {
        int n4 = BATCH * SEQ * DIM / 4;
        split_kernel<<<(n4 + 255) / 256, 256>>>((const float4*)x, (float4*)xh, (float4*)xl, n4);
        dim3 tg(DIM / 32, DIM / 32), tb(32, 8);
        transpose_split_kernel<<<tg, tb>>>(wq, wqh, wql);
        transpose_split_kernel<<<tg, tb>>>(wk, wkh, wkl);
        transpose_split_kernel<<<tg, tb>>>(wv, wvh, wvl);
    }

    const long long sBSD = (long long)SEQ * DIM;
    const long long sSS  = (long long)SEQ * SEQ;

    // 3) Q/K projections: [8192,1024] = x @ Wq, split outputs
    {
        dim3 grid(DIM / BN, (BATCH * SEQ) / BM, 1);
        mma_gemm<7><<<grid, 256, GEMM_SMEM>>>(xh, xl, wqh, wql, Qh, Ql,
                                              DIM, DIM, 0, 0, 0, 1);
        mma_gemm<7><<<grid, 256, GEMM_SMEM>>>(xh, xl, wkh, wkl, Kh, Kl,
                                              DIM, DIM, 0, 0, 0, 1);
    }

    // 4) Vt[b][d][s] = sum_k Wv^T[d][k] * x[b][s][k], split outputs
    {
        dim3 grid(SEQ / BN, DIM / BM, BATCH);
        mma_gemm<7><<<grid, 256, GEMM_SMEM>>>(wvh, wvl, xh, xl, Vth, Vtl,
                                              DIM, SEQ, 0, sBSD, sBSD, 1);
    }

    // 5) scores: P[b] = Q[b] @ K[b]^T (fp32-grade via x3)
    {
        dim3 grid(SEQ / BN, SEQ / BM, BATCH);
        mma_gemm<7><<<grid, 256, GEMM_SMEM>>>(Qh, Ql, Kh, Kl, P, nullptr,
                                              DIM, SEQ, sBSD, sBSD, sSS, 0);
    }

    // 6) masked scaled softmax -> Ph (tf32-rounded)
    {
        dim3 grid(SEQ, BATCH);
        softmax_kernel<<<grid, 256>>>(mask, P, Ph);
    }

    // 7) out[b] = Ph[b] @ Vt[b]^T  (2-pass: Ph*Vh + Ph*Vl)
    {
        dim3 grid(DIM / BN, SEQ / BM, BATCH);
        mma_gemm<3><<<grid, 256, GEMM_SMEM>>>(Ph, nullptr, Vth, Vtl, out, nullptr,
                                              SEQ, DIM, sSS, sBSD, sBSD, 0);
    }
}

// round 5
// speedup vs baseline: 1.8490x; 1.1799x over previous
#include <cuda_runtime.h>
#include <math.h>
#include <stdint.h>

#define BATCH 4
#define SEQ   2048
#define DIM   1024

// ---------------- GEMM tile configuration ----------------
#define BM 128
#define BN 128
#define BK 32
#define A_T_F 4096                      // floats per A tile (128x32)
#define B_T_F 4096                      // floats per B tile (128x32)
#define STAGE_F (4 * A_T_F)             // A_h, A_l, B_h, B_l
#define GEMM_SMEM (2 * STAGE_F * 4)     // 131072 bytes

// ---------------- scratch (static device globals) ----------------
// x in A-perm; weights (transposed) in B-perm; Q in A-perm; K in B-perm;
// Vt in B-perm; P fp32 row-major; Ph in A-perm.
__device__ float g_xa_hi[BATCH * SEQ * DIM];
__device__ float g_xa_lo[BATCH * SEQ * DIM];
__device__ float g_Wq_hi[DIM * DIM];
__device__ float g_Wq_lo[DIM * DIM];
__device__ float g_Wk_hi[DIM * DIM];
__device__ float g_Wk_lo[DIM * DIM];
__device__ float g_Wv_hi[DIM * DIM];
__device__ float g_Wv_lo[DIM * DIM];
__device__ float g_Q_hi[BATCH * SEQ * DIM];
__device__ float g_Q_lo[BATCH * SEQ * DIM];
__device__ float g_K_hi[BATCH * SEQ * DIM];
__device__ float g_K_lo[BATCH * SEQ * DIM];
__device__ float g_Vt_hi[BATCH * DIM * SEQ];
__device__ float g_Vt_lo[BATCH * DIM * SEQ];
__device__ float g_P [(long long)BATCH * SEQ * SEQ];
__device__ float g_Ph[(long long)BATCH * SEQ * SEQ];
__device__ int   g_mask_is_i32;

// ---------------- helpers ----------------
__device__ __forceinline__ uint32_t smem_u32(const void* p) {
    uint32_t a;
    asm("{ .reg .u64 t; cvta.to.shared.u64 t, %1; cvt.u32.u64 %0, t; }" : "=r"(a) : "l"(p));
    return a;
}
__device__ __forceinline__ float f32_to_tf32(float x) {
    uint32_t u;
    asm("cvt.rna.tf32.f32 %0, %1;" : "=r"(u) : "f"(x));
    return __uint_as_float(u);
}
__device__ __forceinline__ void cpasync16(uint32_t dst, const float* src) {
    asm volatile("{ .reg .u64 g; cvta.to.global.u64 g, %1; "
                 "cp.async.cg.shared.global [%0], [g], 16; }"
                 :: "r"(dst), "l"(src) : "memory");
}
__device__ __forceinline__ void cp_commit() {
    asm volatile("cp.async.commit_group;" ::: "memory");
}
__device__ __forceinline__ void mma8(float* c, const uint32_t* a, const uint32_t* b) {
    asm volatile(
        "mma.sync.aligned.m16n8k8.row.col.f32.tf32.tf32.f32 "
        "{%0,%1,%2,%3}, {%4,%5,%6,%7}, {%8,%9}, {%0,%1,%2,%3};"
        : "+f"(c[0]), "+f"(c[1]), "+f"(c[2]), "+f"(c[3])
        : "r"(a[0]), "r"(a[1]), "r"(a[2]), "r"(a[3]), "r"(b[0]), "r"(b[1]));
}

// Permuted-layout index helpers.
// A-perm for [M,K]: fragment block 16m x 8k; one LDS.128/lane = a0..a3.
__device__ __forceinline__ int apidx(int m, int k, int Kc) {
    return ((((m >> 4) * (Kc >> 3) + (k >> 3)) << 7) |
            ((m & 7) << 4) | ((k & 3) << 2) | (((k >> 2) & 1) << 1) | ((m >> 3) & 1));
}
// B-perm for [N,K]: fragment block 8n x 8k; one LDS.64/lane = b0,b1.
__device__ __forceinline__ int bpidx(int n, int k, int Kc) {
    return ((((n >> 3) * (Kc >> 3) + (k >> 3)) << 6) |
            ((n & 7) << 3) | ((k & 3) << 1) | ((k >> 2) & 1));
}

// ============================================================================
// tf32 split NT GEMM on permuted operands: C[m,n] = sum_k A[m,k]*B[n,k]
//   PM bit0: Ah*Bh  bit1: Ah*Bl  bit2: Al*Bh
//   EM: 0 = plain fp32 C (row-major, ldC)
//       1 = split -> A-perm (C=hi, C2=lo), consumer K = Kc
//       2 = split -> B-perm (C=hi, C2=lo), consumer K = Kc
//       3 = split -> B-perm of C^T (Vt), batch stride sC derived from row index
// ============================================================================
template <int PM, int EM>
__global__ __launch_bounds__(256, 1)
void mma_gemm(const float* __restrict__ Ah, const float* __restrict__ Al,
              const float* __restrict__ Bh, const float* __restrict__ Bl,
              float* __restrict__ C, float* __restrict__ C2,
              int Kdim, int ldC, int Kc,
              long long sA, long long sB, long long sC)
{
    extern __shared__ float sm[];
    const int tid  = threadIdx.x;
    const int wid  = tid >> 5;
    const int lane = tid & 31;
    const int gid  = lane >> 2;
    const int tg   = lane & 3;
    const int wm   = wid & 1;
    const int wn   = wid >> 1;

    Ah += blockIdx.z * sA;
    if (PM & 4) Al += blockIdx.z * sA;
    Bh += blockIdx.z * sB;
    if (PM & 2) Bl += blockIdx.z * sB;
    if (EM != 3) { C += blockIdx.z * sC; if (C2) C2 += blockIdx.z * sC; }

    const int row0 = blockIdx.y * BM;
    const int col0 = blockIdx.x * BN;
    const int NC   = Kdim / BK;
    const int KB   = Kdim >> 3;        // K blocks of 8
    const int mb0  = row0 >> 4;
    const int nb0  = col0 >> 3;
    const uint32_t sbase = smem_u32(sm);

    float acc[4][4][4];
#pragma unroll
    for (int i = 0; i < 4; i++)
#pragma unroll
        for (int j = 0; j < 4; j++)
#pragma unroll
            for (int r = 0; r < 4; r++) acc[i][j][r] = 0.f;

    // ---- async tile loader: operands already fragment-permuted in GMEM ----
    auto issue = [&](int c, int buf) {
        const int kb0 = c * 4;
        const uint32_t st = sbase + (uint32_t)buf * (STAGE_F * 4);
        // A tiles: 32 blocks x 128 floats; 16B unit = one lane's 4 regs
#pragma unroll
        for (int i = 0; i < 4; i++) {
            const int u   = tid + i * 256;
            const int blk = u >> 5, ln = u & 31;
            const int g   = ((mb0 + (blk >> 2)) * KB + kb0 + (blk & 3)) * 128 + ln * 4;
            cpasync16(st + u * 16, Ah + g);
            if (PM & 4) cpasync16(st + A_T_F * 4 + u * 16, Al + g);
        }
        // B tiles: 64 blocks x 64 floats; 16B unit = 2 lanes' 2 regs
#pragma unroll
        for (int i = 0; i < 4; i++) {
            const int u   = tid + i * 256;
            const int blk = u >> 4, w = u & 15;
            const int g   = ((nb0 + (blk >> 2)) * KB + kb0 + (blk & 3)) * 64 + w * 4;
            cpasync16(st + 2 * A_T_F * 4 + u * 16, Bh + g);
            if (PM & 2) cpasync16(st + 3 * A_T_F * 4 + u * 16, Bl + g);
        }
        cp_commit();
    };

    issue(0, 0);
    issue(1, 1);

    const int abase = wm * 2048 + lane * 4;   // (wm*4 blocks)*128 + lane*4
    const int bbase = wn * 1024 + lane * 2;   // (wn*4 blocks)*64 + lane*2

    for (int c = 0; c < NC; c++) {
        if (c + 1 < NC) asm volatile("cp.async.wait_group 1;" ::: "memory");
        else            asm volatile("cp.async.wait_group 0;" ::: "memory");
        __syncthreads();

        const float* S = sm + (c & 1) * STAGE_F;
        const uint32_t* sAh = (const uint32_t*)S;
        const uint32_t* sAl = sAh + A_T_F;
        const uint32_t* sBh = sAl + A_T_F;
        const uint32_t* sBl = sBh + B_T_F;

#pragma unroll
        for (int ks = 0; ks < 4; ks++) {
            uint4 a_h[4], a_l[4];
            uint2 b_h[4], b_l[4];
#pragma unroll
            for (int i = 0; i < 4; i++) {
                const int off = abase + (i * 4 + ks) * 128;
                a_h[i] = *(const uint4*)(sAh + off);
                if (PM & 4) a_l[i] = *(const uint4*)(sAl + off);
            }
#pragma unroll
            for (int j = 0; j < 4; j++) {
                const int off = bbase + (j * 4 + ks) * 64;
                b_h[j] = *(const uint2*)(sBh + off);
                if (PM & 2) b_l[j] = *(const uint2*)(sBl + off);
            }
#pragma unroll
            for (int i = 0; i < 4; i++)
#pragma unroll
                for (int j = 0; j < 4; j++) {
                    mma8(acc[i][j], (const uint32_t*)&a_h[i], (const uint32_t*)&b_h[j]);
                    if (PM & 2) mma8(acc[i][j], (const uint32_t*)&a_h[i], (const uint32_t*)&b_l[j]);
                    if (PM & 4) mma8(acc[i][j], (const uint32_t*)&a_l[i], (const uint32_t*)&b_h[j]);
                }
        }
        __syncthreads();
        if (c + 2 < NC) issue(c + 2, c & 1);
    }

    // ---- epilogue ----
#pragma unroll
    for (int i = 0; i < 4; i++) {
        const int r0 = row0 + wm * 64 + i * 16 + gid;
#pragma unroll
        for (int j = 0; j < 4; j++) {
            const int cc = col0 + wn * 32 + j * 8 + tg * 2;
            const float v[4] = {acc[i][j][0], acc[i][j][1], acc[i][j][2], acc[i][j][3]};
            if (EM == 0) {
                *(float2*)(C + (long long)r0 * ldC + cc)       = make_float2(v[0], v[1]);
                *(float2*)(C + (long long)(r0 + 8) * ldC + cc) = make_float2(v[2], v[3]);
            } else {
#pragma unroll
                for (int q = 0; q < 4; q++) {
                    const int m = r0 + (q >> 1) * 8;
                    const int k = cc + (q & 1);
                    const float h = f32_to_tf32(v[q]);
                    const float l = f32_to_tf32(v[q] - h);
                    if (EM == 1) {
                        const int idx = apidx(m, k, Kc);
                        C[idx] = h; C2[idx] = l;
                    } else if (EM == 2) {
                        const int idx = bpidx(m, k, Kc);
                        C[idx] = h; C2[idx] = l;
                    } else {  // EM == 3: Vt = C^T, per-batch base from row index
                        const long long base = (long long)(m >> 11) * sC;
                        const int idx = bpidx(k, m & 2047, Kc);
                        C[base + idx] = h; C2[base + idx] = l;
                    }
                }
            }
        }
    }
}

// ---------------- mask dtype detector ----------------
__global__ void detect_mask_kernel(const int* __restrict__ mask_words) {
    if (blockIdx.x == 0 && threadIdx.x == 0) {
        int ok = 1;
        for (int i = 0; i < 1024; i++) {
            int v = mask_words[i];
            if (v != 0 && v != 1) { ok = 0; break; }
        }
        g_mask_is_i32 = ok;
    }
}

// ---------------- split x -> A-perm hi/lo ----------------
__global__ __launch_bounds__(256)
void split_x_kernel(const float4* __restrict__ in, float* __restrict__ oh,
                    float* __restrict__ ol)
{
    const int i = blockIdx.x * 256 + threadIdx.x;           // float4 index
    const int m  = i >> 8;                                  // row (DIM/4 = 256)
    const int kq = (i & 255) * 4;
    float4 vv = in[i];
    const float vs[4] = {vv.x, vv.y, vv.z, vv.w};
#pragma unroll
    for (int d = 0; d < 4; d++) {
        const int idx = apidx(m, kq + d, DIM);
        const float h = f32_to_tf32(vs[d]);
        oh[idx] = h;
        ol[idx] = f32_to_tf32(vs[d] - h);
    }
}

// ---------------- W[k,n] -> Wt[n,k] B-perm hi/lo ----------------
__global__ __launch_bounds__(256)
void tsplit_w_kernel(const float* __restrict__ W,
                     float* __restrict__ Th, float* __restrict__ Tl)
{
    const int t = blockIdx.x * 256 + threadIdx.x;
    const int k = t >> 10;
    const int n = t & 1023;
    const float v = W[t];
    const float h = f32_to_tf32(v);
    const int idx = bpidx(n, k, DIM);
    Th[idx] = h;
    Tl[idx] = f32_to_tf32(v - h);
}

// ---------------- masked scaled softmax -> Ph in A-perm ----------------
__global__ __launch_bounds__(256)
void softmax_kernel(const void* __restrict__ maskp,
                    const float* __restrict__ P, float* __restrict__ Ph)
{
    const int t = threadIdx.x;
    const int q = blockIdx.x;
    const int b = blockIdx.y;

    const long long rowoff = ((long long)b * SEQ + q) * (long long)SEQ;
    const float* row = P + rowoff;
    float* Pb = Ph + (long long)b * SEQ * SEQ;
    const bool i32 = (g_mask_is_i32 != 0);
    const unsigned char* m8  = (const unsigned char*)maskp + (long long)q * SEQ;
    const int*           m32 = (const int*)maskp           + (long long)q * SEQ;

    float v[8];
    float mx = -INFINITY;
#pragma unroll
    for (int i = 0; i < 8; i++) {
        int j = t + i * 256;
        bool mk = i32 ? (m32[j] != 0) : (m8[j] != 0);
        float s = mk ? -INFINITY : row[j] * 0.03125f;
        v[i] = s;
        mx = fmaxf(mx, s);
    }

    __shared__ float red[256];
    red[t] = mx;
    __syncthreads();
    for (int s = 128; s > 0; s >>= 1) {
        if (t < s) red[t] = fmaxf(red[t], red[t + s]);
        __syncthreads();
    }
    mx = red[0];
    __syncthreads();

    float sum = 0.f;
#pragma unroll
    for (int i = 0; i < 8; i++) {
        float e = expf(v[i] - mx);
        v[i] = e;
        sum += e;
    }
    red[t] = sum;
    __syncthreads();
    for (int s = 128; s > 0; s >>= 1) {
        if (t < s) red[t] += red[t + s];
        __syncthreads();
    }
    float inv = 1.0f / red[0];

#pragma unroll
    for (int i = 0; i < 8; i++) {
        const int j = t + i * 256;
        Pb[apidx(q, j, SEQ)] = f32_to_tf32(v[i] * inv);
    }
}

// ---------------- launch ----------------
extern "C" void kernel_launch(void* const* d_in, const int* in_sizes, int n_in,
                              void* d_out, int out_size)
{
    const float* x    = (const float*)d_in[0];
    const void*  mask = d_in[1];
    const float* wq   = (const float*)d_in[2];
    const float* wk   = (const float*)d_in[3];
    const float* wv   = (const float*)d_in[4];
    float*       out  = (float*)d_out;

    float *xah, *xal, *wqh, *wql, *wkh, *wkl, *wvh, *wvl;
    float *Qh, *Ql, *Kh, *Kl, *Vth, *Vtl, *P, *Ph;
    cudaGetSymbolAddress((void**)&xah, g_xa_hi);
    cudaGetSymbolAddress((void**)&xal, g_xa_lo);
    cudaGetSymbolAddress((void**)&wqh, g_Wq_hi);
    cudaGetSymbolAddress((void**)&wql, g_Wq_lo);
    cudaGetSymbolAddress((void**)&wkh, g_Wk_hi);
    cudaGetSymbolAddress((void**)&wkl, g_Wk_lo);
    cudaGetSymbolAddress((void**)&wvh, g_Wv_hi);
    cudaGetSymbolAddress((void**)&wvl, g_Wv_lo);
    cudaGetSymbolAddress((void**)&Qh,  g_Q_hi);
    cudaGetSymbolAddress((void**)&Ql,  g_Q_lo);
    cudaGetSymbolAddress((void**)&Kh,  g_K_hi);
    cudaGetSymbolAddress((void**)&Kl,  g_K_lo);
    cudaGetSymbolAddress((void**)&Vth, g_Vt_hi);
    cudaGetSymbolAddress((void**)&Vtl, g_Vt_lo);
    cudaGetSymbolAddress((void**)&P,   g_P);
    cudaGetSymbolAddress((void**)&Ph,  g_Ph);

    cudaFuncSetAttribute(mma_gemm<7,1>, cudaFuncAttributeMaxDynamicSharedMemorySize, GEMM_SMEM);
    cudaFuncSetAttribute(mma_gemm<7,2>, cudaFuncAttributeMaxDynamicSharedMemorySize, GEMM_SMEM);
    cudaFuncSetAttribute(mma_gemm<3,3>, cudaFuncAttributeMaxDynamicSharedMemorySize, GEMM_SMEM);
    cudaFuncSetAttribute(mma_gemm<7,0>, cudaFuncAttributeMaxDynamicSharedMemorySize, GEMM_SMEM);
    cudaFuncSetAttribute(mma_gemm<3,0>, cudaFuncAttributeMaxDynamicSharedMemorySize, GEMM_SMEM);

    const long long sBSD = (long long)SEQ * DIM;
    const long long sSS  = (long long)SEQ * SEQ;

    // 1) mask dtype detection
    detect_mask_kernel<<<1, 32>>>((const int*)mask);

    // 2) split x (A-perm); transpose+split weights (B-perm)
    {
        int n4 = BATCH * SEQ * DIM / 4;
        split_x_kernel<<<n4 / 256, 256>>>((const float4*)x, xah, xal);
        int nt = DIM * DIM;
        tsplit_w_kernel<<<nt / 256, 256>>>(wq, wqh, wql);
        tsplit_w_kernel<<<nt / 256, 256>>>(wk, wkh, wkl);
        tsplit_w_kernel<<<nt / 256, 256>>>(wv, wvh, wvl);
    }

    // 3) Q = x @ Wq (x3) -> A-perm split;  K = x @ Wk (x3) -> B-perm split
    {
        dim3 grid(DIM / BN, (BATCH * SEQ) / BM, 1);
        mma_gemm<7,1><<<grid, 256, GEMM_SMEM>>>(xah, xal, wqh, wql, Qh, Ql,
                                                DIM, 0, DIM, 0, 0, 0);
        mma_gemm<7,2><<<grid, 256, GEMM_SMEM>>>(xah, xal, wkh, wkl, Kh, Kl,
                                                DIM, 0, DIM, 0, 0, 0);
    }

    // 4) V = x @ Wv (x2) -> Vt B-perm split (transpose fused in epilogue)
    {
        dim3 grid(DIM / BN, (BATCH * SEQ) / BM, 1);
        mma_gemm<3,3><<<grid, 256, GEMM_SMEM>>>(xah, nullptr, wvh, wvl, Vth, Vtl,
                                                DIM, 0, SEQ, 0, 0, sBSD);
    }

    // 5) scores: P[b] = Q[b] @ K[b]^T (x3), fp32 row-major
    {
        dim3 grid(SEQ / BN, SEQ / BM, BATCH);
        mma_gemm<7,0><<<grid, 256, GEMM_SMEM>>>(Qh, Ql, Kh, Kl, P, nullptr,
                                                DIM, SEQ, 0, sBSD, sBSD, sSS);
    }

    // 6) masked scaled softmax -> Ph (A-perm, tf32-rounded)
    {
        dim3 grid(SEQ, BATCH);
        softmax_kernel<<<grid, 256>>>(mask, P, Ph);
    }

    // 7) out[b] = Ph[b] @ Vt[b]^T (x2: Ph*Vh + Ph*Vl)
    {
        dim3 grid(DIM / BN, SEQ / BM, BATCH);
        mma_gemm<3,0><<<grid, 256, GEMM_SMEM>>>(Ph, nullptr, Vth, Vtl, out, nullptr,
                                                SEQ, DIM, 0, sSS, sBSD, sBSD);
    }
}

// round 6
// speedup vs baseline: 3.0926x; 1.6726x over previous
#include <cuda_runtime.h>
#include <cuda_fp16.h>
#include <math.h>
#include <stdint.h>

#define BATCH 4
#define SEQ   2048
#define DIM   1024

// ---------------- GEMM tile configuration (fp16 operands) ----------------
#define BM 128
#define BN 128
#define BK 64                      // 4 k16 steps per chunk
#define A_T_B 16384                // A tile bytes: 128x64 fp16
#define B_T_B 16384                // B tile bytes: 128x64 fp16
#define STAGE_B (2 * A_T_B + 2 * B_T_B)   // Ah, Al, Bh, Bl = 64 KB
#define NSTAGE 3
#define GEMM_SMEM (NSTAGE * STAGE_B)      // 196608 bytes

// ---------------- scratch (static device globals) ----------------
// x in A-perm fp16; Wt in B-perm fp16; Q A-perm; K B-perm; Vt B-perm;
// P fp32 row-major; Ph fp16 A-perm.
__device__ __half g_xa_hi[BATCH * SEQ * DIM];
__device__ __half g_xa_lo[BATCH * SEQ * DIM];
__device__ __half g_Wq_hi[DIM * DIM];
__device__ __half g_Wq_lo[DIM * DIM];
__device__ __half g_Wk_hi[DIM * DIM];
__device__ __half g_Wk_lo[DIM * DIM];
__device__ __half g_Wv_hi[DIM * DIM];
__device__ __half g_Wv_lo[DIM * DIM];
__device__ __half g_Q_hi[BATCH * SEQ * DIM];
__device__ __half g_Q_lo[BATCH * SEQ * DIM];
__device__ __half g_K_hi[BATCH * SEQ * DIM];
__device__ __half g_K_lo[BATCH * SEQ * DIM];
__device__ __half g_Vt_hi[BATCH * DIM * SEQ];
__device__ __half g_Vt_lo[BATCH * DIM * SEQ];
__device__ float  g_P [(long long)BATCH * SEQ * SEQ];
__device__ __half g_Ph[(long long)BATCH * SEQ * SEQ];
__device__ int    g_mask_is_i32;

// ---------------- helpers ----------------
__device__ __forceinline__ uint32_t smem_u32(const void* p) {
    uint32_t a;
    asm("{ .reg .u64 t; cvta.to.shared.u64 t, %1; cvt.u32.u64 %0, t; }" : "=r"(a) : "l"(p));
    return a;
}
__device__ __forceinline__ void cpasync16(uint32_t dst, const void* src) {
    asm volatile("{ .reg .u64 g; cvta.to.global.u64 g, %1; "
                 "cp.async.cg.shared.global [%0], [g], 16; }"
                 :: "r"(dst), "l"(src) : "memory");
}
__device__ __forceinline__ void cp_commit() {
    asm volatile("cp.async.commit_group;" ::: "memory");
}
// mma m16n8k16 fp16 in, fp32 accum
__device__ __forceinline__ void mma16(float* c, const uint32_t* a, const uint32_t* b) {
    asm volatile(
        "mma.sync.aligned.m16n8k16.row.col.f32.f16.f16.f32 "
        "{%0,%1,%2,%3}, {%4,%5,%6,%7}, {%8,%9}, {%0,%1,%2,%3};"
        : "+f"(c[0]), "+f"(c[1]), "+f"(c[2]), "+f"(c[3])
        : "r"(a[0]), "r"(a[1]), "r"(a[2]), "r"(a[3]), "r"(b[0]), "r"(b[1]));
}

// ---- fragment-permuted fp16 layouts (element index) ----
// A-perm for [M,K]: 16m x 16k blocks (256 fp16 = 512B); one LDS.128/lane = frag a0..a3.
__device__ __forceinline__ int apidx(int m, int k, int Kc) {
    const int blk  = (m >> 4) * (Kc >> 4) + (k >> 4);
    const int lane = (m & 7) * 4 + ((k >> 1) & 3);
    const int q    = ((k >> 3) & 1) * 2 + ((m >> 3) & 1);
    return blk * 256 + lane * 8 + q * 2 + (k & 1);
}
// B-perm for [N,K]: 8n x 16k blocks (128 fp16 = 256B); one LDS.64/lane = frag b0,b1.
__device__ __forceinline__ int bpidx(int n, int k, int Kc) {
    const int blk  = (n >> 3) * (Kc >> 4) + (k >> 4);
    const int lane = (n & 7) * 4 + ((k >> 1) & 3);
    return blk * 128 + lane * 4 + ((k >> 3) & 1) * 2 + (k & 1);
}

// ============================================================================
// fp16 split NT GEMM on permuted operands: C[m,n] = sum_k A[m,k]*B[n,k]
//   PM bit0: Ah*Bh  bit1: Ah*Bl  bit2: Al*Bh
//   EM: 0 = fp32 C row-major (ldC)
//       1 = split -> A-perm fp16 (C=hi, C2=lo), consumer K = Kc
//       2 = split -> B-perm fp16
//       3 = split -> B-perm fp16 of C^T (Vt), batch base from row index
// ============================================================================
template <int PM, int EM>
__global__ __launch_bounds__(256, 1)
void mma_gemm(const __half* __restrict__ Ah, const __half* __restrict__ Al,
              const __half* __restrict__ Bh, const __half* __restrict__ Bl,
              void* __restrict__ Cv, void* __restrict__ C2v,
              int Kdim, int ldC, int Kc,
              long long sA, long long sB, long long sC)
{
    extern __shared__ __align__(16) uint8_t smem[];
    const int tid  = threadIdx.x;
    const int wid  = tid >> 5;
    const int lane = tid & 31;
    const int gid  = lane >> 2;
    const int tg   = lane & 3;
    const int wm   = wid & 1;
    const int wn   = wid >> 1;

    Ah += blockIdx.z * sA;
    if (PM & 4) Al += blockIdx.z * sA;
    Bh += blockIdx.z * sB;
    if (PM & 2) Bl += blockIdx.z * sB;
    float*  Cf  = (float*)Cv;
    __half* Ch  = (__half*)Cv;
    __half* C2h = (__half*)C2v;
    if (EM == 0) Cf += blockIdx.z * sC;
    else if (EM != 3) { Ch += blockIdx.z * sC; C2h += blockIdx.z * sC; }

    const int row0 = blockIdx.y * BM;
    const int col0 = blockIdx.x * BN;
    const int NC   = Kdim / BK;
    const int KB16 = Kdim >> 4;
    const int mb0  = row0 >> 4;
    const int nb0  = col0 >> 3;
    const uint32_t sbase = smem_u32(smem);

    float acc[4][4][4];
#pragma unroll
    for (int i = 0; i < 4; i++)
#pragma unroll
        for (int j = 0; j < 4; j++)
#pragma unroll
            for (int r = 0; r < 4; r++) acc[i][j][r] = 0.f;

    // ---- async tile loader (operands fragment-permuted in GMEM) ----
    auto issue = [&](int c, int buf) {
        const int kb0 = c * 4;                       // 4 k-blocks of 16 per chunk
        const uint32_t st = sbase + (uint32_t)buf * STAGE_B;
        // A tiles: per mbi, 4 consecutive k-blocks = 1024 fp16 contiguous
#pragma unroll
        for (int i = 0; i < 4; i++) {
            const int u   = tid + i * 256;           // 0..1023, 16B units
            const int mbi = u >> 7;
            const int w   = u & 127;
            const long long g = ((long long)(mb0 + mbi) * KB16 + kb0) * 256 + w * 8;
            cpasync16(st + u * 16, Ah + g);
            if (PM & 4) cpasync16(st + A_T_B + u * 16, Al + g);
        }
        // B tiles: per nbi, 4 consecutive k-blocks = 512 fp16 contiguous
#pragma unroll
        for (int i = 0; i < 4; i++) {
            const int u   = tid + i * 256;
            const int nbi = u >> 6;
            const int w   = u & 63;
            const long long g = ((long long)(nb0 + nbi) * KB16 + kb0) * 128 + w * 8;
            cpasync16(st + 2 * A_T_B + u * 16, Bh + g);
            if (PM & 2) cpasync16(st + 3 * A_T_B + u * 16, Bl + g);
        }
        cp_commit();
    };

    issue(0, 0);
    issue(1, 1);
    issue(2, 2);

    const int a_wbase = wm * 2048 + lane * 4;   // b32 units
    const int b_wbase = wn * 1024 + lane * 2;

    int buf = 0;
    for (int c = 0; c < NC; c++) {
        const int rem = NC - c - 1;
        if (rem >= 2)      asm volatile("cp.async.wait_group 2;" ::: "memory");
        else if (rem == 1) asm volatile("cp.async.wait_group 1;" ::: "memory");
        else               asm volatile("cp.async.wait_group 0;" ::: "memory");
        __syncthreads();

        const uint32_t* S   = (const uint32_t*)(smem + buf * STAGE_B);
        const uint32_t* sAh = S;
        const uint32_t* sAl = S + 4096;
        const uint32_t* sBh = S + 8192;
        const uint32_t* sBl = S + 12288;

#pragma unroll
        for (int ks = 0; ks < 4; ks++) {
            uint4 a_h[4], a_l[4];
            uint2 b_h[4], b_l[4];
#pragma unroll
            for (int i = 0; i < 4; i++) {
                const int off = a_wbase + (i * 4 + ks) * 128;
                a_h[i] = *(const uint4*)(sAh + off);
                if (PM & 4) a_l[i] = *(const uint4*)(sAl + off);
            }
#pragma unroll
            for (int j = 0; j < 4; j++) {
                const int off = b_wbase + (j * 4 + ks) * 64;
                b_h[j] = *(const uint2*)(sBh + off);
                if (PM & 2) b_l[j] = *(const uint2*)(sBl + off);
            }
#pragma unroll
            for (int i = 0; i < 4; i++)
#pragma unroll
                for (int j = 0; j < 4; j++) {
                    mma16(acc[i][j], (const uint32_t*)&a_h[i], (const uint32_t*)&b_h[j]);
                    if (PM & 2) mma16(acc[i][j], (const uint32_t*)&a_h[i], (const uint32_t*)&b_l[j]);
                    if (PM & 4) mma16(acc[i][j], (const uint32_t*)&a_l[i], (const uint32_t*)&b_h[j]);
                }
        }
        __syncthreads();
        if (c + 3 < NC) issue(c + 3, buf);
        buf = (buf == 2) ? 0 : buf + 1;
    }

    // ---- epilogue ----
#pragma unroll
    for (int i = 0; i < 4; i++) {
        const int r0 = row0 + wm * 64 + i * 16 + gid;
#pragma unroll
        for (int j = 0; j < 4; j++) {
            const int cc = col0 + wn * 32 + j * 8 + tg * 2;
            const float v[4] = {acc[i][j][0], acc[i][j][1], acc[i][j][2], acc[i][j][3]};
            if (EM == 0) {
                *(float2*)(Cf + (long long)r0 * ldC + cc)       = make_float2(v[0], v[1]);
                *(float2*)(Cf + (long long)(r0 + 8) * ldC + cc) = make_float2(v[2], v[3]);
            } else {
#pragma unroll
                for (int q = 0; q < 4; q++) {
                    const int m = r0 + (q >> 1) * 8;
                    const int k = cc + (q & 1);
                    const __half h = __float2half_rn(v[q]);
                    const __half l = __float2half_rn(v[q] - __half2float(h));
                    if (EM == 1) {
                        const int idx = apidx(m, k, Kc);
                        Ch[idx] = h; C2h[idx] = l;
                    } else if (EM == 2) {
                        const int idx = bpidx(m, k, Kc);
                        Ch[idx] = h; C2h[idx] = l;
                    } else {  // EM == 3: Vt = C^T
                        const long long base = (long long)(m >> 11) * sC;
                        const int idx = bpidx(k, m & 2047, Kc);
                        Ch[base + idx] = h; C2h[base + idx] = l;
                    }
                }
            }
        }
    }
}

// ---------------- mask dtype detector ----------------
__global__ void detect_mask_kernel(const int* __restrict__ mask_words) {
    if (blockIdx.x == 0 && threadIdx.x == 0) {
        int ok = 1;
        for (int i = 0; i < 1024; i++) {
            int v = mask_words[i];
            if (v != 0 && v != 1) { ok = 0; break; }
        }
        g_mask_is_i32 = ok;
    }
}

// ---------------- split x -> A-perm fp16 hi/lo ----------------
__global__ __launch_bounds__(256)
void split_x_kernel(const float4* __restrict__ in, __half* __restrict__ oh,
                    __half* __restrict__ ol)
{
    const int i  = blockIdx.x * 256 + threadIdx.x;   // float4 index
    const int m  = i >> 8;                           // DIM/4 = 256 float4 per row
    const int kq = (i & 255) * 4;
    float4 vv = in[i];
    const float vs[4] = {vv.x, vv.y, vv.z, vv.w};
#pragma unroll
    for (int d = 0; d < 4; d++) {
        const int idx = apidx(m, kq + d, DIM);
        const __half h = __float2half_rn(vs[d]);
        oh[idx] = h;
        ol[idx] = __float2half_rn(vs[d] - __half2float(h));
    }
}

// ---------------- W[k,n] -> Wt[n,k] B-perm fp16 hi/lo ----------------
__global__ __launch_bounds__(256)
void tsplit_w_kernel(const float* __restrict__ W,
                     __half* __restrict__ Th, __half* __restrict__ Tl)
{
    const int t = blockIdx.x * 256 + threadIdx.x;
    const int k = t >> 10;
    const int n = t & 1023;
    const float v = W[t];
    const __half h = __float2half_rn(v);
    const int idx = bpidx(n, k, DIM);
    Th[idx] = h;
    Tl[idx] = __float2half_rn(v - __half2float(h));
}

// ---------------- masked scaled softmax -> Ph fp16 A-perm ----------------
__global__ __launch_bounds__(256)
void softmax_kernel(const void* __restrict__ maskp,
                    const float* __restrict__ P, __half* __restrict__ Ph)
{
    const int t = threadIdx.x;
    const int q = blockIdx.x;
    const int b = blockIdx.y;

    const long long rowoff = ((long long)b * SEQ + q) * (long long)SEQ;
    const float* row = P + rowoff;
    __half* Pb = Ph + (long long)b * SEQ * SEQ;
    const bool i32 = (g_mask_is_i32 != 0);
    const unsigned char* m8  = (const unsigned char*)maskp + (long long)q * SEQ;
    const int*           m32 = (const int*)maskp           + (long long)q * SEQ;

    float v[8];
    float mx = -INFINITY;
#pragma unroll
    for (int i = 0; i < 8; i++) {
        int j = t + i * 256;
        bool mk = i32 ? (m32[j] != 0) : (m8[j] != 0);
        float s = mk ? -INFINITY : row[j] * 0.03125f;
        v[i] = s;
        mx = fmaxf(mx, s);
    }

    __shared__ float red[256];
    red[t] = mx;
    __syncthreads();
    for (int s = 128; s > 0; s >>= 1) {
        if (t < s) red[t] = fmaxf(red[t], red[t + s]);
        __syncthreads();
    }
    mx = red[0];
    __syncthreads();

    float sum = 0.f;
#pragma unroll
    for (int i = 0; i < 8; i++) {
        float e = expf(v[i] - mx);
        v[i] = e;
        sum += e;
    }
    red[t] = sum;
    __syncthreads();
    for (int s = 128; s > 0; s >>= 1) {
        if (t < s) red[t] += red[t + s];
        __syncthreads();
    }
    float inv = 1.0f / red[0];

#pragma unroll
    for (int i = 0; i < 8; i++) {
        const int j = t + i * 256;
        Pb[apidx(q, j, SEQ)] = __float2half_rn(v[i] * inv);
    }
}

// ---------------- launch ----------------
extern "C" void kernel_launch(void* const* d_in, const int* in_sizes, int n_in,
                              void* d_out, int out_size)
{
    const float* x    = (const float*)d_in[0];
    const void*  mask = d_in[1];
    const float* wq   = (const float*)d_in[2];
    const float* wk   = (const float*)d_in[3];
    const float* wv   = (const float*)d_in[4];
    float*       out  = (float*)d_out;

    __half *xah, *xal, *wqh, *wql, *wkh, *wkl, *wvh, *wvl;
    __half *Qh, *Ql, *Kh, *Kl, *Vth, *Vtl, *Ph;
    float *P;
    cudaGetSymbolAddress((void**)&xah, g_xa_hi);
    cudaGetSymbolAddress((void**)&xal, g_xa_lo);
    cudaGetSymbolAddress((void**)&wqh, g_Wq_hi);
    cudaGetSymbolAddress((void**)&wql, g_Wq_lo);
    cudaGetSymbolAddress((void**)&wkh, g_Wk_hi);
    cudaGetSymbolAddress((void**)&wkl, g_Wk_lo);
    cudaGetSymbolAddress((void**)&wvh, g_Wv_hi);
    cudaGetSymbolAddress((void**)&wvl, g_Wv_lo);
    cudaGetSymbolAddress((void**)&Qh,  g_Q_hi);
    cudaGetSymbolAddress((void**)&Ql,  g_Q_lo);
    cudaGetSymbolAddress((void**)&Kh,  g_K_hi);
    cudaGetSymbolAddress((void**)&Kl,  g_K_lo);
    cudaGetSymbolAddress((void**)&Vth, g_Vt_hi);
    cudaGetSymbolAddress((void**)&Vtl, g_Vt_lo);
    cudaGetSymbolAddress((void**)&P,   g_P);
    cudaGetSymbolAddress((void**)&Ph,  g_Ph);

    cudaFuncSetAttribute(mma_gemm<7,1>, cudaFuncAttributeMaxDynamicSharedMemorySize, GEMM_SMEM);
    cudaFuncSetAttribute(mma_gemm<7,2>, cudaFuncAttributeMaxDynamicSharedMemorySize, GEMM_SMEM);
    cudaFuncSetAttribute(mma_gemm<3,3>, cudaFuncAttributeMaxDynamicSharedMemorySize, GEMM_SMEM);
    cudaFuncSetAttribute(mma_gemm<7,0>, cudaFuncAttributeMaxDynamicSharedMemorySize, GEMM_SMEM);
    cudaFuncSetAttribute(mma_gemm<3,0>, cudaFuncAttributeMaxDynamicSharedMemorySize, GEMM_SMEM);

    const long long sBSD = (long long)SEQ * DIM;
    const long long sSS  = (long long)SEQ * SEQ;

    // 1) mask dtype detection
    detect_mask_kernel<<<1, 32>>>((const int*)mask);

    // 2) split x (A-perm); transpose+split weights (B-perm)
    {
        int n4 = BATCH * SEQ * DIM / 4;
        split_x_kernel<<<n4 / 256, 256>>>((const float4*)x, xah, xal);
        int nt = DIM * DIM;
        tsplit_w_kernel<<<nt / 256, 256>>>(wq, wqh, wql);
        tsplit_w_kernel<<<nt / 256, 256>>>(wk, wkh, wkl);
        tsplit_w_kernel<<<nt / 256, 256>>>(wv, wvh, wvl);
    }

    // 3) Q = x @ Wq (x3) -> A-perm split;  K = x @ Wk (x3) -> B-perm split
    {
        dim3 grid(DIM / BN, (BATCH * SEQ) / BM, 1);
        mma_gemm<7,1><<<grid, 256, GEMM_SMEM>>>(xah, xal, wqh, wql, Qh, Ql,
                                                DIM, 0, DIM, 0, 0, 0);
        mma_gemm<7,2><<<grid, 256, GEMM_SMEM>>>(xah, xal, wkh, wkl, Kh, Kl,
                                                DIM, 0, DIM, 0, 0, 0);
    }

    // 4) V = x @ Wv (x2) -> Vt B-perm split (transpose fused in epilogue)
    {
        dim3 grid(DIM / BN, (BATCH * SEQ) / BM, 1);
        mma_gemm<3,3><<<grid, 256, GEMM_SMEM>>>(xah, nullptr, wvh, wvl, Vth, Vtl,
                                                DIM, 0, SEQ, 0, 0, sBSD);
    }

    // 5) scores: P[b] = Q[b] @ K[b]^T (x3), fp32 row-major
    {
        dim3 grid(SEQ / BN, SEQ / BM, BATCH);
        mma_gemm<7,0><<<grid, 256, GEMM_SMEM>>>(Qh, Ql, Kh, Kl, P, nullptr,
                                                DIM, SEQ, 0, sBSD, sBSD, sSS);
    }

    // 6) masked scaled softmax -> Ph (A-perm fp16)
    {
        dim3 grid(SEQ, BATCH);
        softmax_kernel<<<grid, 256>>>(mask, P, Ph);
    }

    // 7) out[b] = Ph[b] @ Vt[b]^T (x2: Ph*Vh + Ph*Vl)
    {
        dim3 grid(DIM / BN, SEQ / BM, BATCH);
        mma_gemm<3,0><<<grid, 256, GEMM_SMEM>>>(Ph, nullptr, Vth, Vtl, out, nullptr,
                                                SEQ, DIM, 0, sSS, sBSD, sBSD);
    }
}

// round 7
// speedup vs baseline: 3.3773x; 1.0920x over previous
#include <cuda_runtime.h>
#include <cuda_fp16.h>
#include <math.h>
#include <stdint.h>

#define BATCH 4
#define SEQ   2048
#define DIM   1024

// ---------------- GEMM tile configuration (fp16 operands) ----------------
#define BM 128
#define BN 128
#define BK 32                      // 2 k16 steps per chunk
#define A_T_B 8192                 // A tile bytes: 128x32 fp16
#define STAGE_B (4 * A_T_B)        // Ah, Al, Bh, Bl = 32 KB
#define NSTAGE 3
#define GEMM_SMEM (NSTAGE * STAGE_B)   // 98304 bytes -> 2 CTAs/SM

// ---------------- scratch (static device globals) ----------------
__device__ __half g_xa_hi[BATCH * SEQ * DIM];
__device__ __half g_xa_lo[BATCH * SEQ * DIM];
__device__ __half g_Wq_hi[DIM * DIM];
__device__ __half g_Wq_lo[DIM * DIM];
__device__ __half g_Wk_hi[DIM * DIM];
__device__ __half g_Wk_lo[DIM * DIM];
__device__ __half g_Wv_hi[DIM * DIM];
__device__ __half g_Wv_lo[DIM * DIM];
__device__ __half g_Q_hi[BATCH * SEQ * DIM];
__device__ __half g_Q_lo[BATCH * SEQ * DIM];
__device__ __half g_K_hi[BATCH * SEQ * DIM];
__device__ __half g_K_lo[BATCH * SEQ * DIM];
__device__ __half g_Vt_hi[BATCH * DIM * SEQ];
__device__ __half g_Vt_lo[BATCH * DIM * SEQ];
__device__ float  g_P [(long long)BATCH * SEQ * SEQ];
__device__ __half g_Ph[(long long)BATCH * SEQ * SEQ];
__device__ int    g_mask_is_i32;

// ---------------- helpers ----------------
__device__ __forceinline__ uint32_t smem_u32(const void* p) {
    uint32_t a;
    asm("{ .reg .u64 t; cvta.to.shared.u64 t, %1; cvt.u32.u64 %0, t; }" : "=r"(a) : "l"(p));
    return a;
}
__device__ __forceinline__ void cpasync16(uint32_t dst, const void* src) {
    asm volatile("{ .reg .u64 g; cvta.to.global.u64 g, %1; "
                 "cp.async.cg.shared.global [%0], [g], 16; }"
                 :: "r"(dst), "l"(src) : "memory");
}
__device__ __forceinline__ void cp_commit() {
    asm volatile("cp.async.commit_group;" ::: "memory");
}
// mma m16n8k16 fp16 in, fp32 accum
__device__ __forceinline__ void mma16(float* c, const uint32_t* a, const uint32_t* b) {
    asm volatile(
        "mma.sync.aligned.m16n8k16.row.col.f32.f16.f16.f32 "
        "{%0,%1,%2,%3}, {%4,%5,%6,%7}, {%8,%9}, {%0,%1,%2,%3};"
        : "+f"(c[0]), "+f"(c[1]), "+f"(c[2]), "+f"(c[3])
        : "r"(a[0]), "r"(a[1]), "r"(a[2]), "r"(a[3]), "r"(b[0]), "r"(b[1]));
}

// ---- fragment-permuted fp16 layouts (element index) ----
// A-perm for [M,K]: 16m x 16k blocks (256 fp16 = 512B); one LDS.128/lane = frag a0..a3.
__device__ __forceinline__ int apidx(int m, int k, int Kc) {
    const int blk  = (m >> 4) * (Kc >> 4) + (k >> 4);
    const int lane = (m & 7) * 4 + ((k >> 1) & 3);
    const int q    = ((k >> 3) & 1) * 2 + ((m >> 3) & 1);
    return blk * 256 + lane * 8 + q * 2 + (k & 1);
}
// B-perm for [N,K]: 8n x 16k blocks (128 fp16 = 256B); one LDS.64/lane = frag b0,b1.
__device__ __forceinline__ int bpidx(int n, int k, int Kc) {
    const int blk  = (n >> 3) * (Kc >> 4) + (k >> 4);
    const int lane = (n & 7) * 4 + ((k >> 1) & 3);
    return blk * 128 + lane * 4 + ((k >> 3) & 1) * 2 + (k & 1);
}

// ============================================================================
// fp16 split NT GEMM on permuted operands: C[m,n] = sum_k A[m,k]*B[n,k]
//   PM bit0: Ah*Bh  bit1: Ah*Bl  bit2: Al*Bh
//   EM: 0 = fp32 C row-major (ldC)
//       1 = split -> A-perm fp16 (C=hi, C2=lo), consumer K = Kc
//       2 = split -> B-perm fp16
//       3 = split -> B-perm fp16 of C^T (Vt), batch base from row index
// ============================================================================
template <int PM, int EM>
__global__ __launch_bounds__(256, 2)
void mma_gemm(const __half* __restrict__ Ah, const __half* __restrict__ Al,
              const __half* __restrict__ Bh, const __half* __restrict__ Bl,
              void* __restrict__ Cv, void* __restrict__ C2v,
              int Kdim, int ldC, int Kc,
              long long sA, long long sB, long long sC)
{
    extern __shared__ __align__(16) uint8_t smem[];
    const int tid  = threadIdx.x;
    const int wid  = tid >> 5;
    const int lane = tid & 31;
    const int gid  = lane >> 2;
    const int tg   = lane & 3;
    const int wm   = wid & 1;
    const int wn   = wid >> 1;

    Ah += blockIdx.z * sA;
    if (PM & 4) Al += blockIdx.z * sA;
    Bh += blockIdx.z * sB;
    if (PM & 2) Bl += blockIdx.z * sB;
    float*  Cf  = (float*)Cv;
    __half* Ch  = (__half*)Cv;
    __half* C2h = (__half*)C2v;
    if (EM == 0) Cf += blockIdx.z * sC;
    else if (EM != 3) { Ch += blockIdx.z * sC; C2h += blockIdx.z * sC; }

    const int row0 = blockIdx.y * BM;
    const int col0 = blockIdx.x * BN;
    const int NC   = Kdim / BK;
    const int KB16 = Kdim >> 4;
    const int mb0  = row0 >> 4;
    const int nb0  = col0 >> 3;
    const uint32_t sbase = smem_u32(smem);

    float acc[4][4][4];
#pragma unroll
    for (int i = 0; i < 4; i++)
#pragma unroll
        for (int j = 0; j < 4; j++)
#pragma unroll
            for (int r = 0; r < 4; r++) acc[i][j][r] = 0.f;

    // ---- async tile loader (operands fragment-permuted in GMEM) ----
    // Chunk = 2 k-blocks of 16. A: 8 m-blocks x 512 fp16 contiguous.
    auto issue = [&](int c, int buf) {
        const int kb0 = c * 2;
        const uint32_t st = sbase + (uint32_t)buf * STAGE_B;
#pragma unroll
        for (int i = 0; i < 2; i++) {
            const int u   = tid + i * 256;           // 0..511 16B units
            const int mbi = u >> 6;
            const int w   = u & 63;
            const long long g = ((long long)(mb0 + mbi) * KB16 + kb0) * 256 + w * 8;
            cpasync16(st + u * 16, Ah + g);
            if (PM & 4) cpasync16(st + A_T_B + u * 16, Al + g);
        }
#pragma unroll
        for (int i = 0; i < 2; i++) {
            const int u   = tid + i * 256;
            const int nbi = u >> 5;
            const int w   = u & 31;
            const long long g = ((long long)(nb0 + nbi) * KB16 + kb0) * 128 + w * 8;
            cpasync16(st + 2 * A_T_B + u * 16, Bh + g);
            if (PM & 2) cpasync16(st + 3 * A_T_B + u * 16, Bl + g);
        }
        cp_commit();
    };

    issue(0, 0);
    issue(1, 1);
    issue(2, 2);

    // smem b32-word bases. A: per m-block 2 k-blocks x 128 words; B: per n-block 2 x 64.
    const int a_wbase = wm * 1024 + lane * 4;
    const int b_wbase = wn * 512 + lane * 2;

    int buf = 0;
    for (int c = 0; c < NC; c++) {
        const int rem = NC - c - 1;
        if (rem >= 2)      asm volatile("cp.async.wait_group 2;" ::: "memory");
        else if (rem == 1) asm volatile("cp.async.wait_group 1;" ::: "memory");
        else               asm volatile("cp.async.wait_group 0;" ::: "memory");
        __syncthreads();

        const uint32_t* S   = (const uint32_t*)(smem + buf * STAGE_B);
        const uint32_t* sAh = S;
        const uint32_t* sAl = S + 2048;
        const uint32_t* sBh = S + 4096;
        const uint32_t* sBl = S + 6144;

#pragma unroll
        for (int ks = 0; ks < 2; ks++) {
            uint4 a_h[4], a_l[4];
            uint2 b_h[4], b_l[4];
#pragma unroll
            for (int i = 0; i < 4; i++) {
                const int off = a_wbase + i * 256 + ks * 128;
                a_h[i] = *(const uint4*)(sAh + off);
                if (PM & 4) a_l[i] = *(const uint4*)(sAl + off);
            }
#pragma unroll
            for (int j = 0; j < 4; j++) {
                const int off = b_wbase + j * 128 + ks * 64;
                b_h[j] = *(const uint2*)(sBh + off);
                if (PM & 2) b_l[j] = *(const uint2*)(sBl + off);
            }
            // pass-outer ordering: same-acc RAW spaced by 16 instructions
#pragma unroll
            for (int i = 0; i < 4; i++)
#pragma unroll
                for (int j = 0; j < 4; j++)
                    mma16(acc[i][j], (const uint32_t*)&a_h[i], (const uint32_t*)&b_h[j]);
            if (PM & 2)
#pragma unroll
                for (int i = 0; i < 4; i++)
#pragma unroll
                    for (int j = 0; j < 4; j++)
                        mma16(acc[i][j], (const uint32_t*)&a_h[i], (const uint32_t*)&b_l[j]);
            if (PM & 4)
#pragma unroll
                for (int i = 0; i < 4; i++)
#pragma unroll
                    for (int j = 0; j < 4; j++)
                        mma16(acc[i][j], (const uint32_t*)&a_l[i], (const uint32_t*)&b_h[j]);
        }
        __syncthreads();
        if (c + 3 < NC) issue(c + 3, buf);
        buf = (buf == 2) ? 0 : buf + 1;
    }

    // ---- epilogue ----
#pragma unroll
    for (int i = 0; i < 4; i++) {
        const int r0 = row0 + wm * 64 + i * 16 + gid;
#pragma unroll
        for (int j = 0; j < 4; j++) {
            const int cc = col0 + wn * 32 + j * 8 + tg * 2;
            const float v[4] = {acc[i][j][0], acc[i][j][1], acc[i][j][2], acc[i][j][3]};
            if (EM == 0) {
                *(float2*)(Cf + (long long)r0 * ldC + cc)       = make_float2(v[0], v[1]);
                *(float2*)(Cf + (long long)(r0 + 8) * ldC + cc) = make_float2(v[2], v[3]);
            } else {
#pragma unroll
                for (int q = 0; q < 4; q++) {
                    const int m = r0 + (q >> 1) * 8;
                    const int k = cc + (q & 1);
                    const __half h = __float2half_rn(v[q]);
                    const __half l = __float2half_rn(v[q] - __half2float(h));
                    if (EM == 1) {
                        const int idx = apidx(m, k, Kc);
                        Ch[idx] = h; C2h[idx] = l;
                    } else if (EM == 2) {
                        const int idx = bpidx(m, k, Kc);
                        Ch[idx] = h; C2h[idx] = l;
                    } else {  // EM == 3: Vt = C^T
                        const long long base = (long long)(m >> 11) * sC;
                        const int idx = bpidx(k, m & 2047, Kc);
                        Ch[base + idx] = h; C2h[base + idx] = l;
                    }
                }
            }
        }
    }
}

// ---------------- mask dtype detector ----------------
__global__ void detect_mask_kernel(const int* __restrict__ mask_words) {
    if (blockIdx.x == 0 && threadIdx.x == 0) {
        int ok = 1;
        for (int i = 0; i < 1024; i++) {
            int v = mask_words[i];
            if (v != 0 && v != 1) { ok = 0; break; }
        }
        g_mask_is_i32 = ok;
    }
}

// ---------------- split x -> A-perm fp16 hi/lo ----------------
__global__ __launch_bounds__(256)
void split_x_kernel(const float4* __restrict__ in, __half* __restrict__ oh,
                    __half* __restrict__ ol)
{
    const int i  = blockIdx.x * 256 + threadIdx.x;
    const int m  = i >> 8;
    const int kq = (i & 255) * 4;
    float4 vv = in[i];
    const float vs[4] = {vv.x, vv.y, vv.z, vv.w};
#pragma unroll
    for (int d = 0; d < 4; d++) {
        const int idx = apidx(m, kq + d, DIM);
        const __half h = __float2half_rn(vs[d]);
        oh[idx] = h;
        ol[idx] = __float2half_rn(vs[d] - __half2float(h));
    }
}

// ---------------- W[k,n] -> Wt[n,k] B-perm fp16 hi/lo ----------------
__global__ __launch_bounds__(256)
void tsplit_w_kernel(const float* __restrict__ W,
                     __half* __restrict__ Th, __half* __restrict__ Tl)
{
    const int t = blockIdx.x * 256 + threadIdx.x;
    const int k = t >> 10;
    const int n = t & 1023;
    const float v = W[t];
    const __half h = __float2half_rn(v);
    const int idx = bpidx(n, k, DIM);
    Th[idx] = h;
    Tl[idx] = __float2half_rn(v - __half2float(h));
}

// ---------------- masked scaled softmax -> Ph fp16 A-perm ----------------
__global__ __launch_bounds__(256)
void softmax_kernel(const void* __restrict__ maskp,
                    const float* __restrict__ P, __half* __restrict__ Ph)
{
    const int t = threadIdx.x;
    const int q = blockIdx.x;
    const int b = blockIdx.y;

    const long long rowoff = ((long long)b * SEQ + q) * (long long)SEQ;
    const float* row = P + rowoff;
    __half* Pb = Ph + (long long)b * SEQ * SEQ;
    const bool i32 = (g_mask_is_i32 != 0);
    const unsigned char* m8  = (const unsigned char*)maskp + (long long)q * SEQ;
    const int*           m32 = (const int*)maskp           + (long long)q * SEQ;

    float v[8];
    float mx = -INFINITY;
#pragma unroll
    for (int i = 0; i < 8; i++) {
        int j = t + i * 256;
        bool mk = i32 ? (m32[j] != 0) : (m8[j] != 0);
        float s = mk ? -INFINITY : row[j] * 0.03125f;
        v[i] = s;
        mx = fmaxf(mx, s);
    }

    __shared__ float red[256];
    red[t] = mx;
    __syncthreads();
    for (int s = 128; s > 0; s >>= 1) {
        if (t < s) red[t] = fmaxf(red[t], red[t + s]);
        __syncthreads();
    }
    mx = red[0];
    __syncthreads();

    float sum = 0.f;
#pragma unroll
    for (int i = 0; i < 8; i++) {
        float e = expf(v[i] - mx);
        v[i] = e;
        sum += e;
    }
    red[t] = sum;
    __syncthreads();
    for (int s = 128; s > 0; s >>= 1) {
        if (t < s) red[t] += red[t + s];
        __syncthreads();
    }
    float inv = 1.0f / red[0];

#pragma unroll
    for (int i = 0; i < 8; i++) {
        const int j = t + i * 256;
        Pb[apidx(q, j, SEQ)] = __float2half_rn(v[i] * inv);
    }
}

// ---------------- launch ----------------
extern "C" void kernel_launch(void* const* d_in, const int* in_sizes, int n_in,
                              void* d_out, int out_size)
{
    const float* x    = (const float*)d_in[0];
    const void*  mask = d_in[1];
    const float* wq   = (const float*)d_in[2];
    const float* wk   = (const float*)d_in[3];
    const float* wv   = (const float*)d_in[4];
    float*       out  = (float*)d_out;

    __half *xah, *xal, *wqh, *wql, *wkh, *wkl, *wvh, *wvl;
    __half *Qh, *Ql, *Kh, *Kl, *Vth, *Vtl, *Ph;
    float *P;
    cudaGetSymbolAddress((void**)&xah, g_xa_hi);
    cudaGetSymbolAddress((void**)&xal, g_xa_lo);
    cudaGetSymbolAddress((void**)&wqh, g_Wq_hi);
    cudaGetSymbolAddress((void**)&wql, g_Wq_lo);
    cudaGetSymbolAddress((void**)&wkh, g_Wk_hi);
    cudaGetSymbolAddress((void**)&wkl, g_Wk_lo);
    cudaGetSymbolAddress((void**)&wvh, g_Wv_hi);
    cudaGetSymbolAddress((void**)&wvl, g_Wv_lo);
    cudaGetSymbolAddress((void**)&Qh,  g_Q_hi);
    cudaGetSymbolAddress((void**)&Ql,  g_Q_lo);
    cudaGetSymbolAddress((void**)&Kh,  g_K_hi);
    cudaGetSymbolAddress((void**)&Kl,  g_K_lo);
    cudaGetSymbolAddress((void**)&Vth, g_Vt_hi);
    cudaGetSymbolAddress((void**)&Vtl, g_Vt_lo);
    cudaGetSymbolAddress((void**)&P,   g_P);
    cudaGetSymbolAddress((void**)&Ph,  g_Ph);

    cudaFuncSetAttribute(mma_gemm<7,1>, cudaFuncAttributeMaxDynamicSharedMemorySize, GEMM_SMEM);
    cudaFuncSetAttribute(mma_gemm<7,2>, cudaFuncAttributeMaxDynamicSharedMemorySize, GEMM_SMEM);
    cudaFuncSetAttribute(mma_gemm<3,3>, cudaFuncAttributeMaxDynamicSharedMemorySize, GEMM_SMEM);
    cudaFuncSetAttribute(mma_gemm<7,0>, cudaFuncAttributeMaxDynamicSharedMemorySize, GEMM_SMEM);
    cudaFuncSetAttribute(mma_gemm<3,0>, cudaFuncAttributeMaxDynamicSharedMemorySize, GEMM_SMEM);

    const long long sBSD = (long long)SEQ * DIM;
    const long long sSS  = (long long)SEQ * SEQ;

    // 1) mask dtype detection
    detect_mask_kernel<<<1, 32>>>((const int*)mask);

    // 2) split x (A-perm); transpose+split weights (B-perm)
    {
        int n4 = BATCH * SEQ * DIM / 4;
        split_x_kernel<<<n4 / 256, 256>>>((const float4*)x, xah, xal);
        int nt = DIM * DIM;
        tsplit_w_kernel<<<nt / 256, 256>>>(wq, wqh, wql);
        tsplit_w_kernel<<<nt / 256, 256>>>(wk, wkh, wkl);
        tsplit_w_kernel<<<nt / 256, 256>>>(wv, wvh, wvl);
    }

    // 3) Q = x @ Wq (x3) -> A-perm split;  K = x @ Wk (x3) -> B-perm split
    {
        dim3 grid(DIM / BN, (BATCH * SEQ) / BM, 1);
        mma_gemm<7,1><<<grid, 256, GEMM_SMEM>>>(xah, xal, wqh, wql, Qh, Ql,
                                                DIM, 0, DIM, 0, 0, 0);
        mma_gemm<7,2><<<grid, 256, GEMM_SMEM>>>(xah, xal, wkh, wkl, Kh, Kl,
                                                DIM, 0, DIM, 0, 0, 0);
    }

    // 4) V = x @ Wv (x2) -> Vt B-perm split (transpose fused in epilogue)
    {
        dim3 grid(DIM / BN, (BATCH * SEQ) / BM, 1);
        mma_gemm<3,3><<<grid, 256, GEMM_SMEM>>>(xah, nullptr, wvh, wvl, Vth, Vtl,
                                                DIM, 0, SEQ, 0, 0, sBSD);
    }

    // 5) scores: P[b] = Q[b] @ K[b]^T (x3), fp32 row-major
    {
        dim3 grid(SEQ / BN, SEQ / BM, BATCH);
        mma_gemm<7,0><<<grid, 256, GEMM_SMEM>>>(Qh, Ql, Kh, Kl, P, nullptr,
                                                DIM, SEQ, 0, sBSD, sBSD, sSS);
    }

    // 6) masked scaled softmax -> Ph (A-perm fp16)
    {
        dim3 grid(SEQ, BATCH);
        softmax_kernel<<<grid, 256>>>(mask, P, Ph);
    }

    // 7) out[b] = Ph[b] @ Vt[b]^T (x2: Ph*Vh + Ph*Vl)
    {
        dim3 grid(DIM / BN, SEQ / BM, BATCH);
        mma_gemm<3,0><<<grid, 256, GEMM_SMEM>>>(Ph, nullptr, Vth, Vtl, out, nullptr,
                                                SEQ, DIM, 0, sSS, sBSD, sBSD);
    }
}

// round 8
// speedup vs baseline: 3.8946x; 1.1532x over previous
#include <cuda_runtime.h>
#include <cuda_fp16.h>
#include <math.h>
#include <stdint.h>

#define BATCH 4
#define SEQ   2048
#define DIM   1024

// ---------------- GEMM tile configuration (fp16 operands) ----------------
#define BM 128
#define BN 128
#define BK 32                      // 2 k16 steps per chunk
#define A_T_B 8192                 // A tile bytes: 128x32 fp16
#define STAGE_B (4 * A_T_B)        // Ah, Al, Bh, Bl = 32 KB
#define NSTAGE 3
#define GEMM_SMEM (NSTAGE * STAGE_B)   // 98304 bytes -> 2 CTAs/SM

// ---------------- scratch (static device globals) ----------------
__device__ __half g_xa_hi[BATCH * SEQ * DIM];
__device__ __half g_xa_lo[BATCH * SEQ * DIM];
__device__ __half g_Wq_hi[DIM * DIM];
__device__ __half g_Wq_lo[DIM * DIM];
__device__ __half g_Wk_hi[DIM * DIM];
__device__ __half g_Wk_lo[DIM * DIM];
__device__ __half g_Wv_hi[DIM * DIM];
__device__ __half g_Wv_lo[DIM * DIM];
__device__ __half g_Q_hi[BATCH * SEQ * DIM];
__device__ __half g_Q_lo[BATCH * SEQ * DIM];
__device__ __half g_K_hi[BATCH * SEQ * DIM];
__device__ __half g_K_lo[BATCH * SEQ * DIM];
__device__ __half g_Vt_hi[BATCH * DIM * SEQ];
__device__ float  g_P [(long long)BATCH * SEQ * SEQ];
__device__ __half g_Ph[(long long)BATCH * SEQ * SEQ];
__device__ int    g_mask_is_i32;

// ---------------- helpers ----------------
__device__ __forceinline__ uint32_t smem_u32(const void* p) {
    uint32_t a;
    asm("{ .reg .u64 t; cvta.to.shared.u64 t, %1; cvt.u32.u64 %0, t; }" : "=r"(a) : "l"(p));
    return a;
}
__device__ __forceinline__ void cpasync16(uint32_t dst, const void* src) {
    asm volatile("{ .reg .u64 g; cvta.to.global.u64 g, %1; "
                 "cp.async.cg.shared.global [%0], [g], 16; }"
                 :: "r"(dst), "l"(src) : "memory");
}
__device__ __forceinline__ void cp_commit() {
    asm volatile("cp.async.commit_group;" ::: "memory");
}
// mma m16n8k16 fp16 in, fp32 accum
__device__ __forceinline__ void mma16(float* c, const uint32_t* a, const uint32_t* b) {
    asm volatile(
        "mma.sync.aligned.m16n8k16.row.col.f32.f16.f16.f32 "
        "{%0,%1,%2,%3}, {%4,%5,%6,%7}, {%8,%9}, {%0,%1,%2,%3};"
        : "+f"(c[0]), "+f"(c[1]), "+f"(c[2]), "+f"(c[3])
        : "r"(a[0]), "r"(a[1]), "r"(a[2]), "r"(a[3]), "r"(b[0]), "r"(b[1]));
}

// ---- fragment-permuted fp16 layouts (element index) ----
// A-perm for [M,K]: 16m x 16k blocks (256 fp16 = 512B); one LDS.128/lane = frag a0..a3.
__device__ __forceinline__ int apidx(int m, int k, int Kc) {
    const int blk  = (m >> 4) * (Kc >> 4) + (k >> 4);
    const int lane = (m & 7) * 4 + ((k >> 1) & 3);
    const int q    = ((k >> 3) & 1) * 2 + ((m >> 3) & 1);
    return blk * 256 + lane * 8 + q * 2 + (k & 1);
}
// B-perm for [N,K]: 8n x 16k blocks (128 fp16 = 256B); one LDS.64/lane = frag b0,b1.
__device__ __forceinline__ int bpidx(int n, int k, int Kc) {
    const int blk  = (n >> 3) * (Kc >> 4) + (k >> 4);
    const int lane = (n & 7) * 4 + ((k >> 1) & 3);
    return blk * 128 + lane * 4 + ((k >> 3) & 1) * 2 + (k & 1);
}

// ============================================================================
// fp16 split NT GEMM on permuted operands: C[m,n] = sum_k A[m,k]*B[n,k]
//   PM bit0: Ah*Bh  bit1: Ah*Bl  bit2: Al*Bh
//   EM: 0 = fp32 C row-major (ldC)
//       1 = split -> A-perm fp16 (C=hi, C2=lo), consumer K = Kc
//       2 = split -> B-perm fp16
//       3 = -> B-perm fp16 of C^T (Vt), batch base from row index (hi only if !C2)
// ============================================================================
template <int PM, int EM>
__global__ __launch_bounds__(256, 2)
void mma_gemm(const __half* __restrict__ Ah, const __half* __restrict__ Al,
              const __half* __restrict__ Bh, const __half* __restrict__ Bl,
              void* __restrict__ Cv, void* __restrict__ C2v,
              int Kdim, int ldC, int Kc,
              long long sA, long long sB, long long sC)
{
    extern __shared__ __align__(16) uint8_t smem[];
    const int tid  = threadIdx.x;
    const int wid  = tid >> 5;
    const int lane = tid & 31;
    const int gid  = lane >> 2;
    const int tg   = lane & 3;
    const int wm   = wid & 1;
    const int wn   = wid >> 1;

    Ah += blockIdx.z * sA;
    if (PM & 4) Al += blockIdx.z * sA;
    Bh += blockIdx.z * sB;
    if (PM & 2) Bl += blockIdx.z * sB;
    float*  Cf  = (float*)Cv;
    __half* Ch  = (__half*)Cv;
    __half* C2h = (__half*)C2v;
    if (EM == 0) Cf += blockIdx.z * sC;
    else if (EM != 3) { Ch += blockIdx.z * sC; if (C2h) C2h += blockIdx.z * sC; }

    const int row0 = blockIdx.y * BM;
    const int col0 = blockIdx.x * BN;
    const int NC   = Kdim / BK;
    const int KB16 = Kdim >> 4;
    const int mb0  = row0 >> 4;
    const int nb0  = col0 >> 3;
    const uint32_t sbase = smem_u32(smem);

    float acc[4][4][4];
#pragma unroll
    for (int i = 0; i < 4; i++)
#pragma unroll
        for (int j = 0; j < 4; j++)
#pragma unroll
            for (int r = 0; r < 4; r++) acc[i][j][r] = 0.f;

    // ---- async tile loader (operands fragment-permuted in GMEM) ----
    auto issue = [&](int c, int buf) {
        const int kb0 = c * 2;
        const uint32_t st = sbase + (uint32_t)buf * STAGE_B;
#pragma unroll
        for (int i = 0; i < 2; i++) {
            const int u   = tid + i * 256;           // 0..511 16B units
            const int mbi = u >> 6;
            const int w   = u & 63;
            const long long g = ((long long)(mb0 + mbi) * KB16 + kb0) * 256 + w * 8;
            cpasync16(st + u * 16, Ah + g);
            if (PM & 4) cpasync16(st + A_T_B + u * 16, Al + g);
        }
#pragma unroll
        for (int i = 0; i < 2; i++) {
            const int u   = tid + i * 256;
            const int nbi = u >> 5;
            const int w   = u & 31;
            const long long g = ((long long)(nb0 + nbi) * KB16 + kb0) * 128 + w * 8;
            cpasync16(st + 2 * A_T_B + u * 16, Bh + g);
            if (PM & 2) cpasync16(st + 3 * A_T_B + u * 16, Bl + g);
        }
        cp_commit();
    };

    issue(0, 0);
    issue(1, 1);
    issue(2, 2);

    const int a_wbase = wm * 1024 + lane * 4;
    const int b_wbase = wn * 512 + lane * 2;

    int buf = 0;
    for (int c = 0; c < NC; c++) {
        const int rem = NC - c - 1;
        if (rem >= 2)      asm volatile("cp.async.wait_group 2;" ::: "memory");
        else if (rem == 1) asm volatile("cp.async.wait_group 1;" ::: "memory");
        else               asm volatile("cp.async.wait_group 0;" ::: "memory");
        __syncthreads();

        const uint32_t* S   = (const uint32_t*)(smem + buf * STAGE_B);
        const uint32_t* sAh = S;
        const uint32_t* sAl = S + 2048;
        const uint32_t* sBh = S + 4096;
        const uint32_t* sBl = S + 6144;

#pragma unroll
        for (int ks = 0; ks < 2; ks++) {
            uint4 a_h[4], a_l[4];
            uint2 b_h[4], b_l[4];
#pragma unroll
            for (int i = 0; i < 4; i++) {
                const int off = a_wbase + i * 256 + ks * 128;
                a_h[i] = *(const uint4*)(sAh + off);
                if (PM & 4) a_l[i] = *(const uint4*)(sAl + off);
            }
#pragma unroll
            for (int j = 0; j < 4; j++) {
                const int off = b_wbase + j * 128 + ks * 64;
                b_h[j] = *(const uint2*)(sBh + off);
                if (PM & 2) b_l[j] = *(const uint2*)(sBl + off);
            }
            // pass-outer ordering: same-acc RAW spaced by 16 instructions
#pragma unroll
            for (int i = 0; i < 4; i++)
#pragma unroll
                for (int j = 0; j < 4; j++)
                    mma16(acc[i][j], (const uint32_t*)&a_h[i], (const uint32_t*)&b_h[j]);
            if (PM & 2)
#pragma unroll
                for (int i = 0; i < 4; i++)
#pragma unroll
                    for (int j = 0; j < 4; j++)
                        mma16(acc[i][j], (const uint32_t*)&a_h[i], (const uint32_t*)&b_l[j]);
            if (PM & 4)
#pragma unroll
                for (int i = 0; i < 4; i++)
#pragma unroll
                    for (int j = 0; j < 4; j++)
                        mma16(acc[i][j], (const uint32_t*)&a_l[i], (const uint32_t*)&b_h[j]);
        }
        __syncthreads();
        if (c + 3 < NC) issue(c + 3, buf);
        buf = (buf == 2) ? 0 : buf + 1;
    }

    // ---- epilogue ----
#pragma unroll
    for (int i = 0; i < 4; i++) {
        const int r0 = row0 + wm * 64 + i * 16 + gid;
#pragma unroll
        for (int j = 0; j < 4; j++) {
            const int cc = col0 + wn * 32 + j * 8 + tg * 2;
            const float v[4] = {acc[i][j][0], acc[i][j][1], acc[i][j][2], acc[i][j][3]};
            if (EM == 0) {
                *(float2*)(Cf + (long long)r0 * ldC + cc)       = make_float2(v[0], v[1]);
                *(float2*)(Cf + (long long)(r0 + 8) * ldC + cc) = make_float2(v[2], v[3]);
            } else {
#pragma unroll
                for (int q = 0; q < 4; q++) {
                    const int m = r0 + (q >> 1) * 8;
                    const int k = cc + (q & 1);
                    const __half h = __float2half_rn(v[q]);
                    if (EM == 1) {
                        const int idx = apidx(m, k, Kc);
                        Ch[idx] = h;
                        C2h[idx] = __float2half_rn(v[q] - __half2float(h));
                    } else if (EM == 2) {
                        const int idx = bpidx(m, k, Kc);
                        Ch[idx] = h;
                        C2h[idx] = __float2half_rn(v[q] - __half2float(h));
                    } else {  // EM == 3: Vt = C^T (hi only when C2 null)
                        const long long base = (long long)(m >> 11) * sC;
                        const int idx = bpidx(k, m & 2047, Kc);
                        Ch[base + idx] = h;
                        if (C2h) C2h[base + idx] = __float2half_rn(v[q] - __half2float(h));
                    }
                }
            }
        }
    }
}

// ---------------- mask dtype detector ----------------
__global__ void detect_mask_kernel(const int* __restrict__ mask_words) {
    if (blockIdx.x == 0 && threadIdx.x == 0) {
        int ok = 1;
        for (int i = 0; i < 1024; i++) {
            int v = mask_words[i];
            if (v != 0 && v != 1) { ok = 0; break; }
        }
        g_mask_is_i32 = ok;
    }
}

// ---------------- split x -> A-perm fp16 hi/lo ----------------
__global__ __launch_bounds__(256)
void split_x_kernel(const float4* __restrict__ in, __half* __restrict__ oh,
                    __half* __restrict__ ol)
{
    const int i  = blockIdx.x * 256 + threadIdx.x;
    const int m  = i >> 8;
    const int kq = (i & 255) * 4;
    float4 vv = in[i];
    const float vs[4] = {vv.x, vv.y, vv.z, vv.w};
#pragma unroll
    for (int d = 0; d < 4; d++) {
        const int idx = apidx(m, kq + d, DIM);
        const __half h = __float2half_rn(vs[d]);
        oh[idx] = h;
        ol[idx] = __float2half_rn(vs[d] - __half2float(h));
    }
}

// ---------------- W[k,n] -> Wt[n,k] B-perm fp16 hi/lo ----------------
__global__ __launch_bounds__(256)
void tsplit_w_kernel(const float* __restrict__ W,
                     __half* __restrict__ Th, __half* __restrict__ Tl)
{
    const int t = blockIdx.x * 256 + threadIdx.x;
    const int k = t >> 10;
    const int n = t & 1023;
    const float v = W[t];
    const __half h = __float2half_rn(v);
    const int idx = bpidx(n, k, DIM);
    Th[idx] = h;
    if (Tl) Tl[idx] = __float2half_rn(v - __half2float(h));
}

// ---------------- masked scaled softmax -> Ph fp16 A-perm ----------------
__global__ __launch_bounds__(256)
void softmax_kernel(const void* __restrict__ maskp,
                    const float* __restrict__ P, __half* __restrict__ Ph)
{
    const int t = threadIdx.x;
    const int q = blockIdx.x;
    const int b = blockIdx.y;

    const long long rowoff = ((long long)b * SEQ + q) * (long long)SEQ;
    const float* row = P + rowoff;
    __half* Pb = Ph + (long long)b * SEQ * SEQ;
    const bool i32 = (g_mask_is_i32 != 0);
    const unsigned char* m8  = (const unsigned char*)maskp + (long long)q * SEQ;
    const int*           m32 = (const int*)maskp           + (long long)q * SEQ;

    float v[8];
    float mx = -INFINITY;
#pragma unroll
    for (int i = 0; i < 8; i++) {
        int j = t + i * 256;
        bool mk = i32 ? (m32[j] != 0) : (m8[j] != 0);
        float s = mk ? -INFINITY : row[j] * 0.03125f;
        v[i] = s;
        mx = fmaxf(mx, s);
    }

    __shared__ float red[256];
    red[t] = mx;
    __syncthreads();
    for (int s = 128; s > 0; s >>= 1) {
        if (t < s) red[t] = fmaxf(red[t], red[t + s]);
        __syncthreads();
    }
    mx = red[0];
    __syncthreads();

    float sum = 0.f;
#pragma unroll
    for (int i = 0; i < 8; i++) {
        float e = expf(v[i] - mx);
        v[i] = e;
        sum += e;
    }
    red[t] = sum;
    __syncthreads();
    for (int s = 128; s > 0; s >>= 1) {
        if (t < s) red[t] += red[t + s];
        __syncthreads();
    }
    float inv = 1.0f / red[0];

#pragma unroll
    for (int i = 0; i < 8; i++) {
        const int j = t + i * 256;
        Pb[apidx(q, j, SEQ)] = __float2half_rn(v[i] * inv);
    }
}

// ---------------- launch ----------------
extern "C" void kernel_launch(void* const* d_in, const int* in_sizes, int n_in,
                              void* d_out, int out_size)
{
    const float* x    = (const float*)d_in[0];
    const void*  mask = d_in[1];
    const float* wq   = (const float*)d_in[2];
    const float* wk   = (const float*)d_in[3];
    const float* wv   = (const float*)d_in[4];
    float*       out  = (float*)d_out;

    __half *xah, *xal, *wqh, *wql, *wkh, *wkl, *wvh, *wvl;
    __half *Qh, *Ql, *Kh, *Kl, *Vth, *Ph;
    float *P;
    cudaGetSymbolAddress((void**)&xah, g_xa_hi);
    cudaGetSymbolAddress((void**)&xal, g_xa_lo);
    cudaGetSymbolAddress((void**)&wqh, g_Wq_hi);
    cudaGetSymbolAddress((void**)&wql, g_Wq_lo);
    cudaGetSymbolAddress((void**)&wkh, g_Wk_hi);
    cudaGetSymbolAddress((void**)&wkl, g_Wk_lo);
    cudaGetSymbolAddress((void**)&wvh, g_Wv_hi);
    cudaGetSymbolAddress((void**)&wvl, g_Wv_lo);
    cudaGetSymbolAddress((void**)&Qh,  g_Q_hi);
    cudaGetSymbolAddress((void**)&Ql,  g_Q_lo);
    cudaGetSymbolAddress((void**)&Kh,  g_K_hi);
    cudaGetSymbolAddress((void**)&Kl,  g_K_lo);
    cudaGetSymbolAddress((void**)&Vth, g_Vt_hi);
    cudaGetSymbolAddress((void**)&P,   g_P);
    cudaGetSymbolAddress((void**)&Ph,  g_Ph);

    cudaFuncSetAttribute(mma_gemm<7,1>, cudaFuncAttributeMaxDynamicSharedMemorySize, GEMM_SMEM);
    cudaFuncSetAttribute(mma_gemm<7,2>, cudaFuncAttributeMaxDynamicSharedMemorySize, GEMM_SMEM);
    cudaFuncSetAttribute(mma_gemm<1,3>, cudaFuncAttributeMaxDynamicSharedMemorySize, GEMM_SMEM);
    cudaFuncSetAttribute(mma_gemm<7,0>, cudaFuncAttributeMaxDynamicSharedMemorySize, GEMM_SMEM);
    cudaFuncSetAttribute(mma_gemm<1,0>, cudaFuncAttributeMaxDynamicSharedMemorySize, GEMM_SMEM);

    const long long sBSD = (long long)SEQ * DIM;
    const long long sSS  = (long long)SEQ * SEQ;

    // 1) mask dtype detection
    detect_mask_kernel<<<1, 32>>>((const int*)mask);

    // 2) split x (A-perm); transpose+split weights (B-perm; Wv hi-only)
    {
        int n4 = BATCH * SEQ * DIM / 4;
        split_x_kernel<<<n4 / 256, 256>>>((const float4*)x, xah, xal);
        int nt = DIM * DIM;
        tsplit_w_kernel<<<nt / 256, 256>>>(wq, wqh, wql);
        tsplit_w_kernel<<<nt / 256, 256>>>(wk, wkh, wkl);
        tsplit_w_kernel<<<nt / 256, 256>>>(wv, wvh, (__half*)nullptr);
    }

    // 3) Q = x @ Wq (x3) -> A-perm split;  K = x @ Wk (x3) -> B-perm split
    {
        dim3 grid(DIM / BN, (BATCH * SEQ) / BM, 1);
        mma_gemm<7,1><<<grid, 256, GEMM_SMEM>>>(xah, xal, wqh, wql, Qh, Ql,
                                                DIM, 0, DIM, 0, 0, 0);
        mma_gemm<7,2><<<grid, 256, GEMM_SMEM>>>(xah, xal, wkh, wkl, Kh, Kl,
                                                DIM, 0, DIM, 0, 0, 0);
    }

    // 4) V = x @ Wv (x1) -> Vt B-perm, hi only (transpose fused in epilogue)
    {
        dim3 grid(DIM / BN, (BATCH * SEQ) / BM, 1);
        mma_gemm<1,3><<<grid, 256, GEMM_SMEM>>>(xah, nullptr, wvh, nullptr, Vth, nullptr,
                                                DIM, 0, SEQ, 0, 0, sBSD);
    }

    // 5) scores: P[b] = Q[b] @ K[b]^T (x3), fp32 row-major
    {
        dim3 grid(SEQ / BN, SEQ / BM, BATCH);
        mma_gemm<7,0><<<grid, 256, GEMM_SMEM>>>(Qh, Ql, Kh, Kl, P, nullptr,
                                                DIM, SEQ, 0, sBSD, sBSD, sSS);
    }

    // 6) masked scaled softmax -> Ph (A-perm fp16)
    {
        dim3 grid(SEQ, BATCH);
        softmax_kernel<<<grid, 256>>>(mask, P, Ph);
    }

    // 7) out[b] = Ph[b] @ Vt[b]^T (x1)
    {
        dim3 grid(DIM / BN, SEQ / BM, BATCH);
        mma_gemm<1,0><<<grid, 256, GEMM_SMEM>>>(Ph, nullptr, Vth, nullptr, out, nullptr,
                                                SEQ, DIM, 0, sSS, sBSD, sBSD);
    }
}